// round 2
// baseline (speedup 1.0000x reference)
#include <cuda_runtime.h>
#include <cstdint>
#include <cstdio>

// Problem constants
#define E_    131072
#define NN_   8192
#define G_    64
#define ED_   2049
#define KIN_  2055      // ED + 6
#define EMB_  625
#define HID_  128
#define OUT_  2
#define EPSF  1e-5f
#define HP    640       // padded pitch for h buffers

// ---------------- device scratch (allocation-free) ----------------
__device__ float g_h1[(size_t)E_ * HP];      // ping
__device__ float g_h2[(size_t)E_ * HP];      // pong
__device__ float g_Wf1p[EMB_ * HID_];        // diag(s3) @ Wf1
__device__ float g_s1[EMB_], g_t1[EMB_];
__device__ float g_s2[EMB_], g_t2[EMB_];
__device__ float g_s3[EMB_], g_t3[EMB_];
__device__ int   g_ebatch[E_];
__device__ float g_cnt[G_];
__device__ float g_gsum[G_ * HID_];

// ---------------- prep kernels ----------------
__global__ void prep0_kernel(const float* __restrict__ g1, const float* __restrict__ be1,
                             const float* __restrict__ m1, const float* __restrict__ v1,
                             const float* __restrict__ g2, const float* __restrict__ be2,
                             const float* __restrict__ m2, const float* __restrict__ v2,
                             const float* __restrict__ g3, const float* __restrict__ be3,
                             const float* __restrict__ m3, const float* __restrict__ v3)
{
    int i = blockIdx.x * blockDim.x + threadIdx.x;
    if (i < EMB_) {
        float s1 = g1[i] / sqrtf(v1[i] + EPSF);
        g_s1[i] = s1; g_t1[i] = be1[i] - m1[i] * s1;
        float s2 = g2[i] / sqrtf(v2[i] + EPSF);
        g_s2[i] = s2; g_t2[i] = be2[i] - m2[i] * s2;
        float s3 = g3[i] / sqrtf(v3[i] + EPSF);
        g_s3[i] = s3; g_t3[i] = be3[i] - m3[i] * s3;
    }
    if (i < G_) g_cnt[i] = 0.0f;
    if (i < G_ * HID_) g_gsum[i] = 0.0f;
}

__global__ void prep_wf1p_kernel(const float* __restrict__ Wf1)
{
    int i = blockIdx.x * blockDim.x + threadIdx.x;
    if (i < EMB_ * HID_) {
        int k = i / HID_;
        g_Wf1p[i] = g_s3[k] * Wf1[i];
    }
}

__global__ void prep_edge_kernel(const int* __restrict__ eidx,
                                 const int* __restrict__ batch)
{
    int e = blockIdx.x * blockDim.x + threadIdx.x;
    if (e < E_) {
        int b = batch[eidx[e]];   // batch[src[e]]
        g_ebatch[e] = b;
        atomicAdd(&g_cnt[b], 1.0f);
    }
}

// ---------------- fused GEMM ----------------
// C[M x N] = epilogue( A[M x K] @ B[K x N] )
//   gather=1: A is the virtual [edge_attr | array[src] | array[dst]] matrix
//   emode 0: h = max(z + bias, 0) * scale + shift  -> store C
//   emode 1: h = max(z + bias, 0)                  -> store C
//   emode 2: atomicAdd(g_gsum[ebatch[row]*HID + n], z)   (N == 128)
#define BM 128
#define BN 128
#define BK 16

__global__ __launch_bounds__(256, 2)
void gemm_fused(const float* __restrict__ A, int lda,
                const float* __restrict__ B, int ldb,
                const float* __restrict__ bias,
                const float* __restrict__ scale,
                const float* __restrict__ shift,
                float* __restrict__ C, int ldc,
                int N, int K, int emode, int gather,
                const float* __restrict__ edge_attr,
                const float* __restrict__ arr,
                const int* __restrict__ eidx)
{
    __shared__ float As[BK][BM + 4];   // +4 pad: keeps float4 alignment, reduces STS conflicts
    __shared__ float Bs[BK][BN];

    const int tid = threadIdx.x;
    const int tx = tid & 15;           // 0..15  -> N direction
    const int ty = tid >> 4;           // 0..15  -> M direction
    const int row0 = blockIdx.y * BM;
    const int col0 = blockIdx.x * BN;

    float acc[8][8];
#pragma unroll
    for (int i = 0; i < 8; i++)
#pragma unroll
        for (int j = 0; j < 8; j++) acc[i][j] = 0.0f;

    const int ktiles = (K + BK - 1) / BK;
    for (int kt = 0; kt < ktiles; kt++) {
        const int k0 = kt * BK;

        // ---- load A tile: 128 rows x 16 k, 8 elems / thread ----
#pragma unroll
        for (int i = 0; i < 8; i++) {
            int lin = tid + i * 256;
            int r  = lin >> 4;          // 0..127
            int kq = lin & 15;          // 0..15
            int kg = k0 + kq;
            int grow = row0 + r;
            float v;
            if (gather) {
                if (kg < ED_) {
                    v = edge_attr[(size_t)grow * ED_ + kg];
                } else if (kg < ED_ + 3) {
                    int s = eidx[grow];
                    v = arr[(size_t)s * 3 + (kg - ED_)];
                } else if (kg < ED_ + 6) {
                    int d = eidx[E_ + grow];
                    v = arr[(size_t)d * 3 + (kg - ED_ - 3)];
                } else {
                    v = 0.0f;
                }
            } else {
                v = (kg < K) ? A[(size_t)grow * lda + kg] : 0.0f;
            }
            As[kq][r] = v;
        }

        // ---- load B tile: 16 k x 128 n, 8 elems / thread (coalesced in n) ----
#pragma unroll
        for (int i = 0; i < 8; i++) {
            int lin = tid + i * 256;
            int kq = lin >> 7;          // 0..15
            int n  = lin & 127;         // 0..127
            int kg = k0 + kq;
            int ng = col0 + n;
            Bs[kq][n] = (kg < K && ng < N) ? B[(size_t)kg * ldb + ng] : 0.0f;
        }
        __syncthreads();

        // ---- compute ----
#pragma unroll
        for (int k = 0; k < BK; k++) {
            float4 a0 = *(const float4*)&As[k][ty * 8];
            float4 a1 = *(const float4*)&As[k][ty * 8 + 4];
            float4 b0 = *(const float4*)&Bs[k][tx * 8];
            float4 b1 = *(const float4*)&Bs[k][tx * 8 + 4];
            float a[8] = {a0.x, a0.y, a0.z, a0.w, a1.x, a1.y, a1.z, a1.w};
            float b[8] = {b0.x, b0.y, b0.z, b0.w, b1.x, b1.y, b1.z, b1.w};
#pragma unroll
            for (int i = 0; i < 8; i++)
#pragma unroll
                for (int j = 0; j < 8; j++)
                    acc[i][j] = fmaf(a[i], b[j], acc[i][j]);
        }
        __syncthreads();
    }

    // ---- epilogue ----
    const int gcol0 = col0 + tx * 8;
    if (emode == 2) {
#pragma unroll
        for (int i = 0; i < 8; i++) {
            int grow = row0 + ty * 8 + i;
            int b = g_ebatch[grow];
            float* dst = &g_gsum[b * HID_];
#pragma unroll
            for (int j = 0; j < 8; j++) {
                atomicAdd(dst + gcol0 + j, acc[i][j]);
            }
        }
    } else {
#pragma unroll
        for (int i = 0; i < 8; i++) {
            int grow = row0 + ty * 8 + i;
            float* crow = C + (size_t)grow * ldc;
#pragma unroll
            for (int j = 0; j < 8; j++) {
                int n = gcol0 + j;
                if (n < N) {
                    float z = acc[i][j] + bias[n];
                    z = fmaxf(z, 0.0f);
                    if (emode == 0) z = z * scale[n] + shift[n];
                    crow[n] = z;
                }
            }
        }
    }
}

// ---------------- head: mean + 2-layer MLP ----------------
__global__ void head_kernel(const float* __restrict__ Wf1,
                            const float* __restrict__ bf1,
                            const float* __restrict__ Wf2,
                            const float* __restrict__ bf2,
                            float* __restrict__ out)
{
    const int g = blockIdx.x;     // 0..63
    const int n = threadIdx.x;    // 0..127
    float cnt = g_cnt[g];
    float v;
    if (cnt > 0.0f) {
        // c0[n] = t3 @ Wf1[:, n]   (constant from folding layer-3 BN into Wf1)
        float c0 = 0.0f;
        for (int k = 0; k < EMB_; k++) c0 = fmaf(g_t3[k], Wf1[k * HID_ + n], c0);
        v = g_gsum[g * HID_ + n] / cnt + c0;
    } else {
        v = 0.0f;   // matches reference: gf = 0 -> gf@Wf1 = 0
    }
    float h = fmaxf(v + bf1[n], 0.0f);

    __shared__ float s0[HID_], s1[HID_];
    s0[n] = h * Wf2[n * OUT_ + 0];
    s1[n] = h * Wf2[n * OUT_ + 1];
    __syncthreads();
    for (int off = HID_ / 2; off > 0; off >>= 1) {
        if (n < off) { s0[n] += s0[n + off]; s1[n] += s1[n + off]; }
        __syncthreads();
    }
    if (n == 0) {
        out[g * OUT_ + 0] = s0[0] + bf2[0];
        out[g * OUT_ + 1] = s1[0] + bf2[1];
    }
}

// ---------------- launch ----------------
extern "C" void kernel_launch(void* const* d_in, const int* in_sizes, int n_in,
                              void* d_out, int out_size)
{
    (void)in_sizes; (void)n_in; (void)out_size;

    const float* edge_attr = (const float*)d_in[0];
    const float* arr       = (const float*)d_in[1];
    const int*   eidx      = (const int*)d_in[2];
    const int*   batch     = (const int*)d_in[3];
    const float *W1 = (const float*)d_in[4],  *b1 = (const float*)d_in[5];
    const float *g1 = (const float*)d_in[6],  *be1 = (const float*)d_in[7];
    const float *m1 = (const float*)d_in[8],  *v1 = (const float*)d_in[9];
    const float *W2 = (const float*)d_in[10], *b2 = (const float*)d_in[11];
    const float *g2 = (const float*)d_in[12], *be2 = (const float*)d_in[13];
    const float *m2 = (const float*)d_in[14], *v2 = (const float*)d_in[15];
    const float *W3 = (const float*)d_in[16], *b3 = (const float*)d_in[17];
    const float *g3 = (const float*)d_in[18], *be3 = (const float*)d_in[19];
    const float *m3 = (const float*)d_in[20], *v3 = (const float*)d_in[21];
    const float *Wf1 = (const float*)d_in[22], *bf1 = (const float*)d_in[23];
    const float *Wf2 = (const float*)d_in[24], *bf2 = (const float*)d_in[25];
    float* out = (float*)d_out;

    float *h1, *h2, *wf1p, *s1p, *t1p, *s2p, *t2p;
    cudaGetSymbolAddress((void**)&h1,   g_h1);
    cudaGetSymbolAddress((void**)&h2,   g_h2);
    cudaGetSymbolAddress((void**)&wf1p, g_Wf1p);
    cudaGetSymbolAddress((void**)&s1p,  g_s1);
    cudaGetSymbolAddress((void**)&t1p,  g_t1);
    cudaGetSymbolAddress((void**)&s2p,  g_s2);
    cudaGetSymbolAddress((void**)&t2p,  g_t2);

    // prep: BN folds, zero accumulators, edge->graph map + counts, folded Wf1'
    prep0_kernel<<<32, 256>>>(g1, be1, m1, v1, g2, be2, m2, v2, g3, be3, m3, v3);
    prep_edge_kernel<<<E_ / 256, 256>>>(eidx, batch);
    prep_wf1p_kernel<<<(EMB_ * HID_ + 255) / 256, 256>>>(Wf1);

    dim3 blk(256);
    dim3 grid5((EMB_ + BN - 1) / BN, E_ / BM);   // (5, 1024)
    dim3 grid1(1, E_ / BM);                      // (1, 1024)

    // Layer 1: gather-concat @ W1 -> relu -> BN affine -> h1
    gemm_fused<<<grid5, blk>>>(nullptr, 0, W1, EMB_, b1, s1p, t1p,
                               h1, HP, EMB_, KIN_, /*emode=*/0, /*gather=*/1,
                               edge_attr, arr, eidx);
    // Layer 2: h1 @ W2 -> relu -> BN affine -> h2
    gemm_fused<<<grid5, blk>>>(h1, HP, W2, EMB_, b2, s2p, t2p,
                               h2, HP, EMB_, EMB_, 0, 0, nullptr, nullptr, nullptr);
    // Layer 3: h2 @ W3 -> relu -> r3 (BN affine folded into Wf1') -> h1
    gemm_fused<<<grid5, blk>>>(h2, HP, W3, EMB_, b3, nullptr, nullptr,
                               h1, HP, EMB_, EMB_, 1, 0, nullptr, nullptr, nullptr);
    // Pool projection: r3 @ Wf1' -> atomic segment-sum into g_gsum[64 x 128]
    gemm_fused<<<grid1, blk>>>(h1, HP, wf1p, HID_, nullptr, nullptr, nullptr,
                               nullptr, 0, HID_, EMB_, 2, 0, nullptr, nullptr, nullptr);
    // Head: mean + c0 + bf1 -> relu -> @ Wf2 + bf2
    head_kernel<<<G_, HID_>>>(Wf1, bf1, Wf2, bf2, out);
}

// round 3
// speedup vs baseline: 1.0340x; 1.0340x over previous
#include <cuda_runtime.h>
#include <cstdint>
#include <cstdio>

// Problem constants
#define E_    131072
#define NN_   8192
#define G_    64
#define ED_   2049
#define KIN_  2055      // ED + 6
#define EMB_  625
#define HID_  128
#define OUT_  2
#define EPSF  1e-5f
#define HP    640       // padded pitch for h buffers

// ---------------- device scratch (allocation-free) ----------------
__device__ float g_h1[(size_t)E_ * HP];      // ping
__device__ float g_h2[(size_t)E_ * HP];      // pong
__device__ float g_Wf1p[EMB_ * HID_];        // diag(s3) @ Wf1
__device__ float g_s1[EMB_], g_t1[EMB_];
__device__ float g_s2[EMB_], g_t2[EMB_];
__device__ float g_s3[EMB_], g_t3[EMB_];
__device__ int   g_ebatch[E_];
__device__ float g_cnt[G_];
__device__ float g_gsum[G_ * HID_];

// ---------------- prep kernels ----------------
__global__ void prep0_kernel(const float* __restrict__ g1, const float* __restrict__ be1,
                             const float* __restrict__ m1, const float* __restrict__ v1,
                             const float* __restrict__ g2, const float* __restrict__ be2,
                             const float* __restrict__ m2, const float* __restrict__ v2,
                             const float* __restrict__ g3, const float* __restrict__ be3,
                             const float* __restrict__ m3, const float* __restrict__ v3)
{
    int i = blockIdx.x * blockDim.x + threadIdx.x;
    if (i < EMB_) {
        float s1 = g1[i] / sqrtf(v1[i] + EPSF);
        g_s1[i] = s1; g_t1[i] = be1[i] - m1[i] * s1;
        float s2 = g2[i] / sqrtf(v2[i] + EPSF);
        g_s2[i] = s2; g_t2[i] = be2[i] - m2[i] * s2;
        float s3 = g3[i] / sqrtf(v3[i] + EPSF);
        g_s3[i] = s3; g_t3[i] = be3[i] - m3[i] * s3;
    }
    if (i < G_) g_cnt[i] = 0.0f;
    if (i < G_ * HID_) g_gsum[i] = 0.0f;
}

__global__ void prep_wf1p_kernel(const float* __restrict__ Wf1)
{
    int i = blockIdx.x * blockDim.x + threadIdx.x;
    if (i < EMB_ * HID_) {
        int k = i / HID_;
        g_Wf1p[i] = g_s3[k] * Wf1[i];
    }
}

__global__ void prep_edge_kernel(const int* __restrict__ eidx,
                                 const int* __restrict__ batch)
{
    int e = blockIdx.x * blockDim.x + threadIdx.x;
    if (e < E_) {
        int b = batch[eidx[e]];   // batch[src[e]]
        g_ebatch[e] = b;
        atomicAdd(&g_cnt[b], 1.0f);
    }
}

// ---------------- TF32 helpers ----------------
__device__ __forceinline__ uint32_t f2tf32(float f) {
    uint32_t u;
    asm("cvt.rna.tf32.f32 %0, %1;" : "=r"(u) : "f"(f));
    return u;
}

#define MMA_TF32(d, a, b0, b1)                                          \
    asm volatile(                                                       \
        "mma.sync.aligned.m16n8k8.row.col.f32.tf32.tf32.f32 "           \
        "{%0,%1,%2,%3}, {%4,%5,%6,%7}, {%8,%9}, {%0,%1,%2,%3};"         \
        : "+f"(d[0]), "+f"(d[1]), "+f"(d[2]), "+f"(d[3])                \
        : "r"(a[0]), "r"(a[1]), "r"(a[2]), "r"(a[3]), "r"(b0), "r"(b1))

// ---------------- fused TF32 tensor-core GEMM ----------------
// C[M x N] = epilogue( A[M x K] @ B[K x N] ), M tiles of 128, N tiles of 128
//   gather=1: A is the virtual [edge_attr | array[src] | array[dst]] matrix
//   emode 0: h = max(z + bias, 0) * scale + shift  -> store C
//   emode 1: h = max(z + bias, 0)                  -> store C
//   emode 2: atomicAdd(g_gsum[ebatch[row]*HID + n], z)   (N == 128)
#define BM 128
#define BN 128
#define BK 32
#define APITCH 36      // As pitch (floats): bank map (4*row + k) % 32, conflict-free frag reads
#define BPITCH 136     // Bs pitch (floats): bank map (8*k + n) % 32, conflict-free frag reads

__global__ __launch_bounds__(256, 2)
void gemm_tf32(const float* __restrict__ A, int lda,
               const float* __restrict__ B, int ldb,
               const float* __restrict__ bias,
               const float* __restrict__ scale,
               const float* __restrict__ shift,
               float* __restrict__ C, int ldc,
               int N, int K, int emode, int gather,
               const float* __restrict__ edge_attr,
               const float* __restrict__ arr,
               const int* __restrict__ eidx)
{
    __shared__ uint32_t As[BM][APITCH];   // [row][k]  (tf32 bit patterns)
    __shared__ uint32_t Bs[BK][BPITCH];   // [k][n]

    const int tid  = threadIdx.x;
    const int lane = tid & 31;
    const int w    = tid >> 5;            // warp 0..7
    const int g    = lane >> 2;           // 0..7
    const int tg   = lane & 3;            // 0..3
    const int wm   = (w & 3) * 32;        // 4 warps in M
    const int wn   = (w >> 2) * 64;       // 2 warps in N

    const int row0 = blockIdx.y * BM;
    const int col0 = blockIdx.x * BN;

    float acc[2][8][4];
#pragma unroll
    for (int mi = 0; mi < 2; mi++)
#pragma unroll
        for (int ni = 0; ni < 8; ni++)
#pragma unroll
            for (int c = 0; c < 4; c++) acc[mi][ni][c] = 0.0f;

    const int ktiles = (K + BK - 1) / BK;
    for (int kt = 0; kt < ktiles; kt++) {
        const int k0 = kt * BK;

        // ---- stage A tile (128 rows x 32 k) ----
        if (gather) {
            // scalar gather path: thread covers (row = lin/32, k = lin%32), coalesced in k
#pragma unroll
            for (int i = 0; i < 16; i++) {
                int lin = tid + i * 256;
                int r   = lin >> 5;
                int kq  = lin & 31;
                int kg  = k0 + kq;
                int grow = row0 + r;
                float v;
                if (kg < ED_) {
                    v = edge_attr[(size_t)grow * ED_ + kg];
                } else if (kg < ED_ + 3) {
                    int s = eidx[grow];
                    v = arr[(size_t)s * 3 + (kg - ED_)];
                } else if (kg < ED_ + 6) {
                    int d = eidx[E_ + grow];
                    v = arr[(size_t)d * 3 + (kg - ED_ - 3)];
                } else {
                    v = 0.0f;
                }
                As[r][kq] = f2tf32(v);
            }
        } else if (k0 + BK <= K) {
            // vector path: float4 per thread x4
#pragma unroll
            for (int i = 0; i < 4; i++) {
                int s  = tid + i * 256;
                int r  = s >> 3;
                int kq = (s & 7) * 4;
                float4 v = *(const float4*)(A + (size_t)(row0 + r) * lda + k0 + kq);
                As[r][kq + 0] = f2tf32(v.x);
                As[r][kq + 1] = f2tf32(v.y);
                As[r][kq + 2] = f2tf32(v.z);
                As[r][kq + 3] = f2tf32(v.w);
            }
        } else {
#pragma unroll
            for (int i = 0; i < 16; i++) {
                int lin = tid + i * 256;
                int r   = lin >> 5;
                int kq  = lin & 31;
                int kg  = k0 + kq;
                float v = (kg < K) ? A[(size_t)(row0 + r) * lda + kg] : 0.0f;
                As[r][kq] = f2tf32(v);
            }
        }

        // ---- stage B tile (32 k x 128 n), coalesced in n ----
#pragma unroll
        for (int i = 0; i < 16; i++) {
            int lin = tid + i * 256;
            int kq  = lin >> 7;
            int n   = lin & 127;
            int kg  = k0 + kq;
            int ng  = col0 + n;
            float v = (kg < K && ng < N) ? B[(size_t)kg * ldb + ng] : 0.0f;
            Bs[kq][n] = f2tf32(v);
        }
        __syncthreads();

        // ---- compute: 4 k8-steps, 16 mma each per warp ----
#pragma unroll
        for (int k8 = 0; k8 < 4; k8++) {
            const int kb = k8 * 8;
            uint32_t a[2][4];
#pragma unroll
            for (int mi = 0; mi < 2; mi++) {
                int r = wm + mi * 16 + g;
                a[mi][0] = As[r][kb + tg];
                a[mi][1] = As[r + 8][kb + tg];
                a[mi][2] = As[r][kb + tg + 4];
                a[mi][3] = As[r + 8][kb + tg + 4];
            }
#pragma unroll
            for (int ni = 0; ni < 8; ni++) {
                int c = wn + ni * 8 + g;
                uint32_t b0 = Bs[kb + tg][c];
                uint32_t b1 = Bs[kb + tg + 4][c];
                MMA_TF32(acc[0][ni], a[0], b0, b1);
                MMA_TF32(acc[1][ni], a[1], b0, b1);
            }
        }
        __syncthreads();
    }

    // ---- epilogue ----
    if (emode == 2) {
#pragma unroll
        for (int mi = 0; mi < 2; mi++) {
            int r0g = row0 + wm + mi * 16 + g;
            int b_lo = g_ebatch[r0g];
            int b_hi = g_ebatch[r0g + 8];
#pragma unroll
            for (int ni = 0; ni < 8; ni++) {
                int cg = col0 + wn + ni * 8 + tg * 2;
                atomicAdd(&g_gsum[b_lo * HID_ + cg],     acc[mi][ni][0]);
                atomicAdd(&g_gsum[b_lo * HID_ + cg + 1], acc[mi][ni][1]);
                atomicAdd(&g_gsum[b_hi * HID_ + cg],     acc[mi][ni][2]);
                atomicAdd(&g_gsum[b_hi * HID_ + cg + 1], acc[mi][ni][3]);
            }
        }
    } else {
#pragma unroll
        for (int mi = 0; mi < 2; mi++) {
            int r_lo = row0 + wm + mi * 16 + g;
            int r_hi = r_lo + 8;
            float* crow_lo = C + (size_t)r_lo * ldc;
            float* crow_hi = C + (size_t)r_hi * ldc;
#pragma unroll
            for (int ni = 0; ni < 8; ni++) {
                int cg = col0 + wn + ni * 8 + tg * 2;
#pragma unroll
                for (int jj = 0; jj < 2; jj++) {
                    int n = cg + jj;
                    if (n < N) {
                        float z0 = acc[mi][ni][jj] + bias[n];
                        z0 = fmaxf(z0, 0.0f);
                        if (emode == 0) z0 = z0 * scale[n] + shift[n];
                        crow_lo[n] = z0;
                        float z1 = acc[mi][ni][jj + 2] + bias[n];
                        z1 = fmaxf(z1, 0.0f);
                        if (emode == 0) z1 = z1 * scale[n] + shift[n];
                        crow_hi[n] = z1;
                    }
                }
            }
        }
    }
}

// ---------------- head: mean + 2-layer MLP ----------------
__global__ void head_kernel(const float* __restrict__ Wf1,
                            const float* __restrict__ bf1,
                            const float* __restrict__ Wf2,
                            const float* __restrict__ bf2,
                            float* __restrict__ out)
{
    const int g = blockIdx.x;     // 0..63
    const int n = threadIdx.x;    // 0..127
    float cnt = g_cnt[g];
    float v;
    if (cnt > 0.0f) {
        // c0[n] = t3 @ Wf1[:, n]   (constant from folding layer-3 BN into Wf1)
        float c0 = 0.0f;
        for (int k = 0; k < EMB_; k++) c0 = fmaf(g_t3[k], Wf1[k * HID_ + n], c0);
        v = g_gsum[g * HID_ + n] / cnt + c0;
    } else {
        v = 0.0f;   // matches reference: gf = 0 -> gf@Wf1 = 0
    }
    float h = fmaxf(v + bf1[n], 0.0f);

    __shared__ float s0[HID_], s1[HID_];
    s0[n] = h * Wf2[n * OUT_ + 0];
    s1[n] = h * Wf2[n * OUT_ + 1];
    __syncthreads();
    for (int off = HID_ / 2; off > 0; off >>= 1) {
        if (n < off) { s0[n] += s0[n + off]; s1[n] += s1[n + off]; }
        __syncthreads();
    }
    if (n == 0) {
        out[g * OUT_ + 0] = s0[0] + bf2[0];
        out[g * OUT_ + 1] = s1[0] + bf2[1];
    }
}

// ---------------- launch ----------------
extern "C" void kernel_launch(void* const* d_in, const int* in_sizes, int n_in,
                              void* d_out, int out_size)
{
    (void)in_sizes; (void)n_in; (void)out_size;

    const float* edge_attr = (const float*)d_in[0];
    const float* arr       = (const float*)d_in[1];
    const int*   eidx      = (const int*)d_in[2];
    const int*   batch     = (const int*)d_in[3];
    const float *W1 = (const float*)d_in[4],  *b1 = (const float*)d_in[5];
    const float *g1 = (const float*)d_in[6],  *be1 = (const float*)d_in[7];
    const float *m1 = (const float*)d_in[8],  *v1 = (const float*)d_in[9];
    const float *W2 = (const float*)d_in[10], *b2 = (const float*)d_in[11];
    const float *g2 = (const float*)d_in[12], *be2 = (const float*)d_in[13];
    const float *m2 = (const float*)d_in[14], *v2 = (const float*)d_in[15];
    const float *W3 = (const float*)d_in[16], *b3 = (const float*)d_in[17];
    const float *g3 = (const float*)d_in[18], *be3 = (const float*)d_in[19];
    const float *m3 = (const float*)d_in[20], *v3 = (const float*)d_in[21];
    const float *Wf1 = (const float*)d_in[22], *bf1 = (const float*)d_in[23];
    const float *Wf2 = (const float*)d_in[24], *bf2 = (const float*)d_in[25];
    float* out = (float*)d_out;

    float *h1, *h2, *wf1p, *s1p, *t1p, *s2p, *t2p;
    cudaGetSymbolAddress((void**)&h1,   g_h1);
    cudaGetSymbolAddress((void**)&h2,   g_h2);
    cudaGetSymbolAddress((void**)&wf1p, g_Wf1p);
    cudaGetSymbolAddress((void**)&s1p,  g_s1);
    cudaGetSymbolAddress((void**)&t1p,  g_t1);
    cudaGetSymbolAddress((void**)&s2p,  g_s2);
    cudaGetSymbolAddress((void**)&t2p,  g_t2);

    // prep: BN folds, zero accumulators, edge->graph map + counts, folded Wf1'
    prep0_kernel<<<32, 256>>>(g1, be1, m1, v1, g2, be2, m2, v2, g3, be3, m3, v3);
    prep_edge_kernel<<<E_ / 256, 256>>>(eidx, batch);
    prep_wf1p_kernel<<<(EMB_ * HID_ + 255) / 256, 256>>>(Wf1);

    dim3 blk(256);
    dim3 grid5((EMB_ + BN - 1) / BN, E_ / BM);   // (5, 1024)
    dim3 grid1(1, E_ / BM);                      // (1, 1024)

    // Layer 1: gather-concat @ W1 -> relu -> BN affine -> h1
    gemm_tf32<<<grid5, blk>>>(nullptr, 0, W1, EMB_, b1, s1p, t1p,
                              h1, HP, EMB_, KIN_, /*emode=*/0, /*gather=*/1,
                              edge_attr, arr, eidx);
    // Layer 2: h1 @ W2 -> relu -> BN affine -> h2
    gemm_tf32<<<grid5, blk>>>(h1, HP, W2, EMB_, b2, s2p, t2p,
                              h2, HP, EMB_, EMB_, 0, 0, nullptr, nullptr, nullptr);
    // Layer 3: h2 @ W3 -> relu -> r3 (BN affine folded into Wf1') -> h1
    gemm_tf32<<<grid5, blk>>>(h2, HP, W3, EMB_, b3, nullptr, nullptr,
                              h1, HP, EMB_, EMB_, 1, 0, nullptr, nullptr, nullptr);
    // Pool projection: r3 @ Wf1' -> atomic segment-sum into g_gsum[64 x 128]
    gemm_tf32<<<grid1, blk>>>(h1, HP, wf1p, HID_, nullptr, nullptr, nullptr,
                              nullptr, 0, HID_, EMB_, 2, 0, nullptr, nullptr, nullptr);
    // Head: mean + c0 + bf1 -> relu -> @ Wf2 + bf2
    head_kernel<<<G_, HID_>>>(Wf1, bf1, Wf2, bf2, out);
}

// round 4
// speedup vs baseline: 5.3135x; 5.1390x over previous
#include <cuda_runtime.h>
#include <cstdint>
#include <cstdio>

// Problem constants
#define E_    131072
#define NN_   8192
#define G_    64
#define ED_   2049
#define KIN_  2055
#define EMB_  625
#define HID_  128
#define OUT_  2
#define EPSF  1e-5f

#define KP1   2080     // padded K for layer 1 (multiple of 32)
#define HP    640      // padded pitch / K for h buffers and weight K-dims
#define STAGES 3
#define STAGE_BYTES 32768   // A 16KB + B 16KB

// ---------------- device scratch (allocation-free) ----------------
__device__ float g_A1[(size_t)E_ * KP1];     // 1.09 GB: tf32-rounded concat input
__device__ float g_h1[(size_t)E_ * HP];      // ping (tf32-rounded activations)
__device__ float g_h2[(size_t)E_ * HP];      // pong
__device__ float g_W1t[HP * KP1];            // Wt[n][k] tf32, padded
__device__ float g_W2t[HP * HP];
__device__ float g_W3t[HP * HP];
__device__ float g_Wf1t[HID_ * HP];          // diag(s3)-folded, transposed
__device__ float g_s1[EMB_], g_t1[EMB_];
__device__ float g_s2[EMB_], g_t2[EMB_];
__device__ float g_s3[EMB_], g_t3[EMB_];
__device__ int   g_ebatch[E_];
__device__ float g_cnt[G_];
__device__ float g_gsum[G_ * HID_];

// ---------------- helpers ----------------
__device__ __forceinline__ uint32_t f2tf32(float f) {
    uint32_t u;
    asm("cvt.rna.tf32.f32 %0, %1;" : "=r"(u) : "f"(f));
    return u;
}
__device__ __forceinline__ float tf32f(float f) { return __uint_as_float(f2tf32(f)); }

__device__ __forceinline__ uint32_t smem_u32(const void* p) {
    return (uint32_t)__cvta_generic_to_shared(p);
}

__device__ __forceinline__ void cp16(uint32_t dst, const void* src) {
    asm volatile("cp.async.cg.shared.global [%0], [%1], 16;\n" :: "r"(dst), "l"(src));
}
#define CP_COMMIT() asm volatile("cp.async.commit_group;\n" ::: "memory")
#define CP_WAIT2()  asm volatile("cp.async.wait_group 2;\n" ::: "memory")

__device__ __forceinline__ void ldsm4(uint32_t& r0, uint32_t& r1, uint32_t& r2, uint32_t& r3,
                                      uint32_t addr) {
    asm volatile("ldmatrix.sync.aligned.m8n8.x4.shared.b16 {%0,%1,%2,%3}, [%4];"
                 : "=r"(r0), "=r"(r1), "=r"(r2), "=r"(r3) : "r"(addr));
}

#define MMA_TF32(d, a, b0, b1)                                          \
    asm volatile(                                                       \
        "mma.sync.aligned.m16n8k8.row.col.f32.tf32.tf32.f32 "           \
        "{%0,%1,%2,%3}, {%4,%5,%6,%7}, {%8,%9}, {%0,%1,%2,%3};"         \
        : "+f"(d[0]), "+f"(d[1]), "+f"(d[2]), "+f"(d[3])                \
        : "r"(a[0]), "r"(a[1]), "r"(a[2]), "r"(a[3]), "r"(b0), "r"(b1))

// ---------------- prep kernels ----------------
__global__ void prep0_kernel(const float* __restrict__ g1, const float* __restrict__ be1,
                             const float* __restrict__ m1, const float* __restrict__ v1,
                             const float* __restrict__ g2, const float* __restrict__ be2,
                             const float* __restrict__ m2, const float* __restrict__ v2,
                             const float* __restrict__ g3, const float* __restrict__ be3,
                             const float* __restrict__ m3, const float* __restrict__ v3)
{
    int i = blockIdx.x * blockDim.x + threadIdx.x;
    if (i < EMB_) {
        float s1 = g1[i] / sqrtf(v1[i] + EPSF);
        g_s1[i] = s1; g_t1[i] = be1[i] - m1[i] * s1;
        float s2 = g2[i] / sqrtf(v2[i] + EPSF);
        g_s2[i] = s2; g_t2[i] = be2[i] - m2[i] * s2;
        float s3 = g3[i] / sqrtf(v3[i] + EPSF);
        g_s3[i] = s3; g_t3[i] = be3[i] - m3[i] * s3;
    }
    if (i < G_) g_cnt[i] = 0.0f;
    if (i < G_ * HID_) g_gsum[i] = 0.0f;
}

__global__ void prep_edge_kernel(const int* __restrict__ eidx,
                                 const int* __restrict__ batch)
{
    int e = blockIdx.x * blockDim.x + threadIdx.x;
    if (e < E_) {
        int b = batch[eidx[e]];
        g_ebatch[e] = b;
        atomicAdd(&g_cnt[b], 1.0f);
    }
}

// Build tf32-rounded concatenated A1[e][0..KP1)
__global__ void build_a1_kernel(const float* __restrict__ ea,
                                const float* __restrict__ arr,
                                const int* __restrict__ eidx)
{
    int e = blockIdx.x;
    float* dst = g_A1 + (size_t)e * KP1;
    for (int k = threadIdx.x; k < KP1; k += blockDim.x) {
        float v;
        if (k < ED_) {
            v = ea[(size_t)e * ED_ + k];
        } else if (k < ED_ + 3) {
            int s = eidx[e];
            v = arr[3 * s + (k - ED_)];
        } else if (k < ED_ + 6) {
            int d = eidx[E_ + e];
            v = arr[3 * d + (k - ED_ - 3)];
        } else {
            v = 0.0f;
        }
        dst[k] = tf32f(v);
    }
}

// Wt[n][k] = tf32( W[k][n] * (scale_k ? s3[k] : 1) ), zero-padded to [NP][KP]
__global__ void prep_wt_kernel(const float* __restrict__ W, int K, int N,
                               float* __restrict__ Wt, int KP, int scale_k)
{
    int k = blockIdx.x * blockDim.x + threadIdx.x;
    int n = blockIdx.y;
    if (k >= KP) return;
    float v = 0.0f;
    if (k < K && n < N) {
        v = W[(size_t)k * N + n];
        if (scale_k) v *= g_s3[k];
    }
    Wt[(size_t)n * KP + k] = tf32f(v);
}

// ---------------- tensor-core GEMM with cp.async pipeline + ldmatrix ----------------
// C[M x N] = epilogue( A[M x Kpad] @ Bt[n][k]^T )
//   emode 0: h = max(z + bias, 0) * scale + shift  -> store tf32-rounded
//   emode 1: h = max(z + bias, 0)                  -> store tf32-rounded
//   emode 2: atomicAdd(g_gsum[ebatch[row]*HID + n], z)
__global__ __launch_bounds__(128)
void gemm_tc(const float* __restrict__ A, int lda,
             const float* __restrict__ Bt, int ldbt,
             const float* __restrict__ bias,
             const float* __restrict__ scale,
             const float* __restrict__ shift,
             float* __restrict__ C, int ldc,
             int N, int ktiles, int emode)
{
    extern __shared__ __align__(16) char smem_raw[];
    const uint32_t sb = smem_u32(smem_raw);

    const int tid  = threadIdx.x;
    const int lane = tid & 31;
    const int w    = tid >> 5;            // 0..3
    const int wm   = (w & 1) * 64;
    const int wn   = (w >> 1) * 64;
    const int row0 = blockIdx.y * 128;
    const int col0 = blockIdx.x * 128;

    const float* Abase = A  + (size_t)row0 * lda;
    const float* Bbase = Bt + (size_t)col0 * ldbt;

    // per-lane ldmatrix address components
    const int rA  = wm + ((lane >> 3) & 1) * 8 + (lane & 7);
    const int hiA = lane >> 4;            // 0/1 : k-chunk select
    const int xa  = rA & 7;
    const int rB  = wn + (lane >> 4) * 8 + (lane & 7);
    const int hiB = (lane >> 3) & 1;
    const int xb  = rB & 7;

    float acc[4][8][4];
#pragma unroll
    for (int mi = 0; mi < 4; mi++)
#pragma unroll
        for (int ni = 0; ni < 8; ni++)
#pragma unroll
            for (int c = 0; c < 4; c++) acc[mi][ni][c] = 0.0f;

    // ---- staging lambda (stage s, ktile kt) ----
    auto stage = [&](int s, int kt) {
        uint32_t sA = sb + s * STAGE_BYTES;
        uint32_t sB = sA + 16384;
        const float* As = Abase + kt * 32;
        const float* Bs = Bbase + kt * 32;
#pragma unroll
        for (int i = 0; i < 8; i++) {
            int id = i * 128 + tid;
            int m  = id >> 3;
            int c  = id & 7;
            cp16(sA + m * 128 + ((c ^ (m & 7)) << 4), As + (size_t)m * lda + c * 4);
        }
#pragma unroll
        for (int i = 0; i < 8; i++) {
            int id = i * 128 + tid;
            int n  = id >> 3;
            int c  = id & 7;
            cp16(sB + n * 128 + ((c ^ (n & 7)) << 4), Bs + (size_t)n * ldbt + c * 4);
        }
    };

    // prologue: stages 0..STAGES-2
#pragma unroll
    for (int s = 0; s < STAGES - 1; s++) {
        if (s < ktiles) stage(s, s);
        CP_COMMIT();
    }

    for (int kt = 0; kt < ktiles; kt++) {
        int pf = kt + STAGES - 1;
        if (pf < ktiles) stage(pf % STAGES, pf);
        CP_COMMIT();
        CP_WAIT2();
        __syncthreads();

        const int s = kt % STAGES;
        const uint32_t sA = sb + s * STAGE_BYTES;
        const uint32_t sB = sA + 16384;

#pragma unroll
        for (int k8 = 0; k8 < 4; k8++) {
            uint32_t a[4][4];
#pragma unroll
            for (int mi = 0; mi < 4; mi++) {
                uint32_t addr = sA + (rA + mi * 16) * 128
                              + ((uint32_t)((k8 * 2 + hiA) ^ xa) << 4);
                ldsm4(a[mi][0], a[mi][1], a[mi][2], a[mi][3], addr);
            }
            uint32_t bf[4][4];
#pragma unroll
            for (int nj = 0; nj < 4; nj++) {
                uint32_t addr = sB + (rB + nj * 16) * 128
                              + ((uint32_t)((k8 * 2 + hiB) ^ xb) << 4);
                ldsm4(bf[nj][0], bf[nj][1], bf[nj][2], bf[nj][3], addr);
            }
#pragma unroll
            for (int mi = 0; mi < 4; mi++) {
#pragma unroll
                for (int nj = 0; nj < 4; nj++) {
                    MMA_TF32(acc[mi][2 * nj],     a[mi], bf[nj][0], bf[nj][1]);
                    MMA_TF32(acc[mi][2 * nj + 1], a[mi], bf[nj][2], bf[nj][3]);
                }
            }
        }
        __syncthreads();
    }

    // ---- epilogue ----
    const int g  = lane >> 2;
    const int tg = lane & 3;
    if (emode == 2) {
#pragma unroll
        for (int mi = 0; mi < 4; mi++) {
            int r_lo = row0 + wm + mi * 16 + g;
            int b_lo = g_ebatch[r_lo];
            int b_hi = g_ebatch[r_lo + 8];
#pragma unroll
            for (int ni = 0; ni < 8; ni++) {
                int cc = wn + ni * 8 + tg * 2;   // col0 == 0 for pool
                atomicAdd(&g_gsum[b_lo * HID_ + cc],     acc[mi][ni][0]);
                atomicAdd(&g_gsum[b_lo * HID_ + cc + 1], acc[mi][ni][1]);
                atomicAdd(&g_gsum[b_hi * HID_ + cc],     acc[mi][ni][2]);
                atomicAdd(&g_gsum[b_hi * HID_ + cc + 1], acc[mi][ni][3]);
            }
        }
    } else {
#pragma unroll
        for (int mi = 0; mi < 4; mi++) {
            int r_lo = row0 + wm + mi * 16 + g;
            float* crow_lo = C + (size_t)r_lo * ldc;
            float* crow_hi = crow_lo + (size_t)8 * ldc;
#pragma unroll
            for (int ni = 0; ni < 8; ni++) {
                int cc = col0 + wn + ni * 8 + tg * 2;
                if (cc + 1 < N) {
                    float b0 = bias[cc], b1 = bias[cc + 1];
                    float z0 = fmaxf(acc[mi][ni][0] + b0, 0.0f);
                    float z1 = fmaxf(acc[mi][ni][1] + b1, 0.0f);
                    float z2 = fmaxf(acc[mi][ni][2] + b0, 0.0f);
                    float z3 = fmaxf(acc[mi][ni][3] + b1, 0.0f);
                    if (emode == 0) {
                        float sc0 = scale[cc], sc1 = scale[cc + 1];
                        float sh0 = shift[cc], sh1 = shift[cc + 1];
                        z0 = z0 * sc0 + sh0;  z1 = z1 * sc1 + sh1;
                        z2 = z2 * sc0 + sh0;  z3 = z3 * sc1 + sh1;
                    }
                    *(float2*)&crow_lo[cc] = make_float2(tf32f(z0), tf32f(z1));
                    *(float2*)&crow_hi[cc] = make_float2(tf32f(z2), tf32f(z3));
                } else if (cc < N) {
                    float b0 = bias[cc];
                    float z0 = fmaxf(acc[mi][ni][0] + b0, 0.0f);
                    float z2 = fmaxf(acc[mi][ni][2] + b0, 0.0f);
                    if (emode == 0) {
                        float sc0 = scale[cc], sh0 = shift[cc];
                        z0 = z0 * sc0 + sh0;  z2 = z2 * sc0 + sh0;
                    }
                    crow_lo[cc] = tf32f(z0);
                    crow_hi[cc] = tf32f(z2);
                }
            }
        }
    }
}

// ---------------- head: mean + 2-layer MLP ----------------
__global__ void head_kernel(const float* __restrict__ Wf1,
                            const float* __restrict__ bf1,
                            const float* __restrict__ Wf2,
                            const float* __restrict__ bf2,
                            float* __restrict__ out)
{
    const int g = blockIdx.x;
    const int n = threadIdx.x;
    float cnt = g_cnt[g];
    float v;
    if (cnt > 0.0f) {
        float c0 = 0.0f;
        for (int k = 0; k < EMB_; k++) c0 = fmaf(g_t3[k], Wf1[k * HID_ + n], c0);
        v = g_gsum[g * HID_ + n] / cnt + c0;
    } else {
        v = 0.0f;
    }
    float h = fmaxf(v + bf1[n], 0.0f);

    __shared__ float s0[HID_], s1[HID_];
    s0[n] = h * Wf2[n * OUT_ + 0];
    s1[n] = h * Wf2[n * OUT_ + 1];
    __syncthreads();
    for (int off = HID_ / 2; off > 0; off >>= 1) {
        if (n < off) { s0[n] += s0[n + off]; s1[n] += s1[n + off]; }
        __syncthreads();
    }
    if (n == 0) {
        out[g * OUT_ + 0] = s0[0] + bf2[0];
        out[g * OUT_ + 1] = s1[0] + bf2[1];
    }
}

// ---------------- launch ----------------
extern "C" void kernel_launch(void* const* d_in, const int* in_sizes, int n_in,
                              void* d_out, int out_size)
{
    (void)in_sizes; (void)n_in; (void)out_size;

    const float* edge_attr = (const float*)d_in[0];
    const float* arr       = (const float*)d_in[1];
    const int*   eidx      = (const int*)d_in[2];
    const int*   batch     = (const int*)d_in[3];
    const float *W1 = (const float*)d_in[4],  *b1 = (const float*)d_in[5];
    const float *g1 = (const float*)d_in[6],  *be1 = (const float*)d_in[7];
    const float *m1 = (const float*)d_in[8],  *v1 = (const float*)d_in[9];
    const float *W2 = (const float*)d_in[10], *b2 = (const float*)d_in[11];
    const float *g2 = (const float*)d_in[12], *be2 = (const float*)d_in[13];
    const float *m2 = (const float*)d_in[14], *v2 = (const float*)d_in[15];
    const float *W3 = (const float*)d_in[16], *b3 = (const float*)d_in[17];
    const float *g3 = (const float*)d_in[18], *be3 = (const float*)d_in[19];
    const float *m3 = (const float*)d_in[20], *v3 = (const float*)d_in[21];
    const float *Wf1 = (const float*)d_in[22], *bf1 = (const float*)d_in[23];
    const float *Wf2 = (const float*)d_in[24], *bf2 = (const float*)d_in[25];
    float* out = (float*)d_out;

    float *a1, *h1, *h2, *w1t, *w2t, *w3t, *wf1t;
    float *s1p, *t1p, *s2p, *t2p;
    cudaGetSymbolAddress((void**)&a1,   g_A1);
    cudaGetSymbolAddress((void**)&h1,   g_h1);
    cudaGetSymbolAddress((void**)&h2,   g_h2);
    cudaGetSymbolAddress((void**)&w1t,  g_W1t);
    cudaGetSymbolAddress((void**)&w2t,  g_W2t);
    cudaGetSymbolAddress((void**)&w3t,  g_W3t);
    cudaGetSymbolAddress((void**)&wf1t, g_Wf1t);
    cudaGetSymbolAddress((void**)&s1p,  g_s1);
    cudaGetSymbolAddress((void**)&t1p,  g_t1);
    cudaGetSymbolAddress((void**)&s2p,  g_s2);
    cudaGetSymbolAddress((void**)&t2p,  g_t2);

    cudaFuncSetAttribute(gemm_tc, cudaFuncAttributeMaxDynamicSharedMemorySize,
                         STAGES * STAGE_BYTES);

    // prep
    prep0_kernel<<<32, 256>>>(g1, be1, m1, v1, g2, be2, m2, v2, g3, be3, m3, v3);
    prep_edge_kernel<<<E_ / 256, 256>>>(eidx, batch);
    build_a1_kernel<<<E_, 256>>>(edge_attr, arr, eidx);
    {
        dim3 gw((KP1 + 255) / 256, HP);
        prep_wt_kernel<<<gw, 256>>>(W1, KIN_, EMB_, w1t, KP1, 0);
    }
    {
        dim3 gw((HP + 255) / 256, HP);
        prep_wt_kernel<<<gw, 256>>>(W2, EMB_, EMB_, w2t, HP, 0);
        prep_wt_kernel<<<gw, 256>>>(W3, EMB_, EMB_, w3t, HP, 0);
    }
    {
        dim3 gw((HP + 255) / 256, HID_);
        prep_wt_kernel<<<gw, 256>>>(Wf1, EMB_, HID_, wf1t, HP, 1);
    }

    const int smem = STAGES * STAGE_BYTES;
    dim3 blk(128);
    dim3 grid5(5, E_ / 128);   // (5, 1024)
    dim3 grid1(1, E_ / 128);

    // Layer 1: A1 @ W1t -> relu -> BN affine -> h1
    gemm_tc<<<grid5, blk, smem>>>(a1, KP1, w1t, KP1, b1, s1p, t1p,
                                  h1, HP, EMB_, KP1 / 32, 0);
    // Layer 2: h1 @ W2t -> relu -> BN affine -> h2
    gemm_tc<<<grid5, blk, smem>>>(h1, HP, w2t, HP, b2, s2p, t2p,
                                  h2, HP, EMB_, HP / 32, 0);
    // Layer 3: h2 @ W3t -> relu -> h1  (BN affine folded into Wf1t)
    gemm_tc<<<grid5, blk, smem>>>(h2, HP, w3t, HP, b3, nullptr, nullptr,
                                  h1, HP, EMB_, HP / 32, 1);
    // Pool projection: h1 @ Wf1t -> atomic segment-sum into g_gsum
    gemm_tc<<<grid1, blk, smem>>>(h1, HP, wf1t, HP, nullptr, nullptr, nullptr,
                                  nullptr, 0, HID_, HP / 32, 2);
    // Head
    head_kernel<<<G_, HID_>>>(Wf1, bf1, Wf2, bf2, out);
}

// round 6
// speedup vs baseline: 8.4771x; 1.5954x over previous
#include <cuda_runtime.h>
#include <cuda_fp16.h>
#include <cstdint>

// Problem constants
#define E_    131072
#define G_    64
#define ED_   2049
#define KIN_  2055
#define EMB_  625
#define HID_  128
#define OUT_  2
#define EPSF  1e-5f

#define KP1   2112     // padded K for layer 1 (multiple of 64)
#define HP    640      // padded N / K pitch for h buffers & weights (10 ktiles of 64)
#define STAGES 3
#define STAGE_BYTES 32768   // A 16KB + B 16KB (128 rows x 128B each, k-tile = 64 halves)

// ---------------- device scratch (allocation-free) ----------------
__device__ __half g_A1[(size_t)E_ * KP1];
__device__ __half g_h1[(size_t)E_ * HP];
__device__ __half g_h2[(size_t)E_ * HP];
__device__ __half g_W1t[HP * KP1];
__device__ __half g_W2t[HP * HP];
__device__ __half g_W3t[HP * HP];
__device__ __half g_Wf1t[HID_ * HP];
__device__ float g_s1[EMB_], g_t1[EMB_];
__device__ float g_s2[EMB_], g_t2[EMB_];
__device__ float g_s3[EMB_], g_t3[EMB_];
__device__ int   g_ebatch[E_];
__device__ float g_cnt[G_];
__device__ float g_gsum[G_ * HID_];

// ---------------- helpers ----------------
__device__ __forceinline__ uint32_t smem_u32(const void* p) {
    return (uint32_t)__cvta_generic_to_shared(p);
}
__device__ __forceinline__ void cp16(uint32_t dst, const void* src) {
    asm volatile("cp.async.cg.shared.global [%0], [%1], 16;\n" :: "r"(dst), "l"(src));
}
#define CP_COMMIT() asm volatile("cp.async.commit_group;\n" ::: "memory")
#define CP_WAIT2()  asm volatile("cp.async.wait_group 2;\n" ::: "memory")

__device__ __forceinline__ void ldsm4(uint32_t& r0, uint32_t& r1, uint32_t& r2, uint32_t& r3,
                                      uint32_t addr) {
    asm volatile("ldmatrix.sync.aligned.m8n8.x4.shared.b16 {%0,%1,%2,%3}, [%4];"
                 : "=r"(r0), "=r"(r1), "=r"(r2), "=r"(r3) : "r"(addr));
}

#define MMA_F16(d, a, b0, b1)                                           \
    asm volatile(                                                       \
        "mma.sync.aligned.m16n8k16.row.col.f32.f16.f16.f32 "            \
        "{%0,%1,%2,%3}, {%4,%5,%6,%7}, {%8,%9}, {%0,%1,%2,%3};"         \
        : "+f"(d[0]), "+f"(d[1]), "+f"(d[2]), "+f"(d[3])                \
        : "r"(a[0]), "r"(a[1]), "r"(a[2]), "r"(a[3]), "r"(b0), "r"(b1))

// ---------------- prep kernels ----------------
__global__ void prep0_kernel(const float* __restrict__ g1, const float* __restrict__ be1,
                             const float* __restrict__ m1, const float* __restrict__ v1,
                             const float* __restrict__ g2, const float* __restrict__ be2,
                             const float* __restrict__ m2, const float* __restrict__ v2,
                             const float* __restrict__ g3, const float* __restrict__ be3,
                             const float* __restrict__ m3, const float* __restrict__ v3)
{
    int i = blockIdx.x * blockDim.x + threadIdx.x;
    if (i < EMB_) {
        float s1 = g1[i] / sqrtf(v1[i] + EPSF);
        g_s1[i] = s1; g_t1[i] = be1[i] - m1[i] * s1;
        float s2 = g2[i] / sqrtf(v2[i] + EPSF);
        g_s2[i] = s2; g_t2[i] = be2[i] - m2[i] * s2;
        float s3 = g3[i] / sqrtf(v3[i] + EPSF);
        g_s3[i] = s3; g_t3[i] = be3[i] - m3[i] * s3;
    }
    if (i < G_) g_cnt[i] = 0.0f;
    if (i < G_ * HID_) g_gsum[i] = 0.0f;
}

__global__ void prep_edge_kernel(const int* __restrict__ eidx,
                                 const int* __restrict__ batch)
{
    int e = blockIdx.x * blockDim.x + threadIdx.x;
    if (e < E_) {
        int b = batch[eidx[e]];
        g_ebatch[e] = b;
        atomicAdd(&g_cnt[b], 1.0f);
    }
}

// Build fp16 concatenated A1[e][0..KP1)
__global__ void build_a1_kernel(const float* __restrict__ ea,
                                const float* __restrict__ arr,
                                const int* __restrict__ eidx)
{
    int e = blockIdx.x;
    __half* dst = g_A1 + (size_t)e * KP1;
    for (int k = threadIdx.x; k < KP1; k += blockDim.x) {
        float v;
        if (k < ED_) {
            v = ea[(size_t)e * ED_ + k];
        } else if (k < ED_ + 3) {
            int s = eidx[e];
            v = arr[3 * s + (k - ED_)];
        } else if (k < ED_ + 6) {
            int d = eidx[E_ + e];
            v = arr[3 * d + (k - ED_ - 3)];
        } else {
            v = 0.0f;
        }
        dst[k] = __float2half_rn(v);
    }
}

// Wt[n][k] = fp16( W[k][n] * (scale_k ? s3[k] : 1) ), zero-padded to [NP][KP]
__global__ void prep_wt_kernel(const float* __restrict__ W, int K, int N,
                               __half* __restrict__ Wt, int KP, int scale_k)
{
    int k = blockIdx.x * blockDim.x + threadIdx.x;
    int n = blockIdx.y;
    if (k >= KP) return;
    float v = 0.0f;
    if (k < K && n < N) {
        v = W[(size_t)k * N + n];
        if (scale_k) v *= g_s3[k];
    }
    Wt[(size_t)n * KP + k] = __float2half_rn(v);
}

// ---------------- fp16 tensor-core GEMM: cp.async pipeline + ldmatrix ----------------
// C[M x 640] tiles of 128x128; A[M x KP] fp16 row-major; Bt[n][k] fp16.
//   emode 0: h = max(z + bias, 0) * scale + shift  -> fp16 store (0 for n >= Nreal)
//   emode 1: h = max(z + bias, 0)                  -> fp16 store
//   emode 2: atomicAdd(g_gsum[ebatch[row]*HID + n], z)
__global__ __launch_bounds__(128)
void gemm_f16(const __half* __restrict__ A, int lda,
              const __half* __restrict__ Bt, int ldbt,
              const float* __restrict__ bias,
              const float* __restrict__ scale,
              const float* __restrict__ shift,
              __half* __restrict__ C, int ldc,
              int Nreal, int ktiles, int emode)
{
    extern __shared__ __align__(16) char smem_raw[];
    const uint32_t sb = smem_u32(smem_raw);

    const int tid  = threadIdx.x;
    const int lane = tid & 31;
    const int w    = tid >> 5;            // 0..3
    const int wm   = (w & 1) * 64;
    const int wn   = (w >> 1) * 64;
    const int row0 = blockIdx.y * 128;
    const int col0 = blockIdx.x * 128;

    const __half* Abase = A  + (size_t)row0 * lda;
    const __half* Bbase = Bt + (size_t)col0 * ldbt;

    // ldmatrix lane address components (8x8 b16 matrices, 16B rows)
    const int rA  = wm + (lane & 15);     // A rows: m0/m1 -> rows, m2/m3 -> k+8
    const int hiA = lane >> 4;            // 0/1: k-halfchunk select
    const int xa  = rA & 7;
    const int rB  = wn + ((lane >> 4) & 1) * 8 + (lane & 7);  // n row
    const int hiB = (lane >> 3) & 1;
    const int xb  = rB & 7;

    float acc[4][8][4];
#pragma unroll
    for (int mi = 0; mi < 4; mi++)
#pragma unroll
        for (int ni = 0; ni < 8; ni++)
#pragma unroll
            for (int c = 0; c < 4; c++) acc[mi][ni][c] = 0.0f;

    // staging: k-tile = 64 halves = 128B per row, XOR-swizzled 16B chunks
    auto stage = [&](int s, int kt) {
        uint32_t sA = sb + s * STAGE_BYTES;
        uint32_t sB = sA + 16384;
        const __half* Ak = Abase + kt * 64;
        const __half* Bk = Bbase + kt * 64;
#pragma unroll
        for (int i = 0; i < 8; i++) {
            int id = i * 128 + tid;
            int m  = id >> 3;
            int c  = id & 7;
            cp16(sA + m * 128 + ((c ^ (m & 7)) << 4), Ak + (size_t)m * lda + c * 8);
        }
#pragma unroll
        for (int i = 0; i < 8; i++) {
            int id = i * 128 + tid;
            int n  = id >> 3;
            int c  = id & 7;
            cp16(sB + n * 128 + ((c ^ (n & 7)) << 4), Bk + (size_t)n * ldbt + c * 8);
        }
    };

    // prologue
#pragma unroll
    for (int s = 0; s < STAGES - 1; s++) {
        if (s < ktiles) stage(s, s);
        CP_COMMIT();
    }

    for (int kt = 0; kt < ktiles; kt++) {
        int pf = kt + STAGES - 1;
        if (pf < ktiles) stage(pf % STAGES, pf);
        CP_COMMIT();
        CP_WAIT2();
        __syncthreads();

        const int s = kt % STAGES;
        const uint32_t sA = sb + s * STAGE_BYTES;
        const uint32_t sB = sA + 16384;

#pragma unroll
        for (int k16 = 0; k16 < 4; k16++) {
            uint32_t a[4][4];
#pragma unroll
            for (int mi = 0; mi < 4; mi++) {
                uint32_t addr = sA + (rA + mi * 16) * 128
                              + ((uint32_t)((k16 * 2 + hiA) ^ xa) << 4);
                ldsm4(a[mi][0], a[mi][1], a[mi][2], a[mi][3], addr);
            }
            uint32_t bf[4][4];
#pragma unroll
            for (int nj = 0; nj < 4; nj++) {
                uint32_t addr = sB + (rB + nj * 16) * 128
                              + ((uint32_t)((k16 * 2 + hiB) ^ xb) << 4);
                ldsm4(bf[nj][0], bf[nj][1], bf[nj][2], bf[nj][3], addr);
            }
#pragma unroll
            for (int mi = 0; mi < 4; mi++) {
#pragma unroll
                for (int nj = 0; nj < 4; nj++) {
                    MMA_F16(acc[mi][2 * nj],     a[mi], bf[nj][0], bf[nj][1]);
                    MMA_F16(acc[mi][2 * nj + 1], a[mi], bf[nj][2], bf[nj][3]);
                }
            }
        }
        __syncthreads();
    }

    // ---- epilogue ----
    const int g  = lane >> 2;
    const int tg = lane & 3;
    if (emode == 2) {
#pragma unroll
        for (int mi = 0; mi < 4; mi++) {
            int r_lo = row0 + wm + mi * 16 + g;
            int b_lo = g_ebatch[r_lo];
            int b_hi = g_ebatch[r_lo + 8];
#pragma unroll
            for (int ni = 0; ni < 8; ni++) {
                int cc = wn + ni * 8 + tg * 2;   // col0 == 0 for pool
                atomicAdd(&g_gsum[b_lo * HID_ + cc],     acc[mi][ni][0]);
                atomicAdd(&g_gsum[b_lo * HID_ + cc + 1], acc[mi][ni][1]);
                atomicAdd(&g_gsum[b_hi * HID_ + cc],     acc[mi][ni][2]);
                atomicAdd(&g_gsum[b_hi * HID_ + cc + 1], acc[mi][ni][3]);
            }
        }
    } else {
#pragma unroll
        for (int mi = 0; mi < 4; mi++) {
            int r_lo = row0 + wm + mi * 16 + g;
            __half* crow_lo = C + (size_t)r_lo * ldc;
            __half* crow_hi = crow_lo + (size_t)8 * ldc;
#pragma unroll
            for (int ni = 0; ni < 8; ni++) {
                int cc = col0 + wn + ni * 8 + tg * 2;
                float z0 = 0.0f, z1 = 0.0f, z2 = 0.0f, z3 = 0.0f;
                if (cc < Nreal) {
                    float b0 = bias[cc];
                    z0 = fmaxf(acc[mi][ni][0] + b0, 0.0f);
                    z2 = fmaxf(acc[mi][ni][2] + b0, 0.0f);
                    if (emode == 0) {
                        float sc0 = scale[cc], sh0 = shift[cc];
                        z0 = z0 * sc0 + sh0;  z2 = z2 * sc0 + sh0;
                    }
                }
                if (cc + 1 < Nreal) {
                    float b1 = bias[cc + 1];
                    z1 = fmaxf(acc[mi][ni][1] + b1, 0.0f);
                    z3 = fmaxf(acc[mi][ni][3] + b1, 0.0f);
                    if (emode == 0) {
                        float sc1 = scale[cc + 1], sh1 = shift[cc + 1];
                        z1 = z1 * sc1 + sh1;  z3 = z3 * sc1 + sh1;
                    }
                }
                *(__half2*)&crow_lo[cc] = __floats2half2_rn(z0, z1);
                *(__half2*)&crow_hi[cc] = __floats2half2_rn(z2, z3);
            }
        }
    }
}

// ---------------- head: mean + 2-layer MLP ----------------
__global__ void head_kernel(const float* __restrict__ Wf1,
                            const float* __restrict__ bf1,
                            const float* __restrict__ Wf2,
                            const float* __restrict__ bf2,
                            float* __restrict__ out)
{
    const int g = blockIdx.x;
    const int n = threadIdx.x;
    float cnt = g_cnt[g];
    float v;
    if (cnt > 0.0f) {
        float c0 = 0.0f;
        for (int k = 0; k < EMB_; k++) c0 = fmaf(g_t3[k], Wf1[k * HID_ + n], c0);
        v = g_gsum[g * HID_ + n] / cnt + c0;
    } else {
        v = 0.0f;
    }
    float h = fmaxf(v + bf1[n], 0.0f);

    __shared__ float s0[HID_], s1[HID_];
    s0[n] = h * Wf2[n * OUT_ + 0];
    s1[n] = h * Wf2[n * OUT_ + 1];
    __syncthreads();
    for (int off = HID_ / 2; off > 0; off >>= 1) {
        if (n < off) { s0[n] += s0[n + off]; s1[n] += s1[n + off]; }
        __syncthreads();
    }
    if (n == 0) {
        out[g * OUT_ + 0] = s0[0] + bf2[0];
        out[g * OUT_ + 1] = s1[0] + bf2[1];
    }
}

// ---------------- launch ----------------
extern "C" void kernel_launch(void* const* d_in, const int* in_sizes, int n_in,
                              void* d_out, int out_size)
{
    (void)in_sizes; (void)n_in; (void)out_size;

    const float* edge_attr = (const float*)d_in[0];
    const float* arr       = (const float*)d_in[1];
    const int*   eidx      = (const int*)d_in[2];
    const int*   batch     = (const int*)d_in[3];
    const float *W1 = (const float*)d_in[4],  *b1 = (const float*)d_in[5];
    const float *g1 = (const float*)d_in[6],  *be1 = (const float*)d_in[7];
    const float *m1 = (const float*)d_in[8],  *v1 = (const float*)d_in[9];
    const float *W2 = (const float*)d_in[10], *b2 = (const float*)d_in[11];
    const float *g2 = (const float*)d_in[12], *be2 = (const float*)d_in[13];
    const float *m2 = (const float*)d_in[14], *v2 = (const float*)d_in[15];
    const float *W3 = (const float*)d_in[16], *b3 = (const float*)d_in[17];
    const float *g3 = (const float*)d_in[18], *be3 = (const float*)d_in[19];
    const float *m3 = (const float*)d_in[20], *v3 = (const float*)d_in[21];
    const float *Wf1 = (const float*)d_in[22], *bf1 = (const float*)d_in[23];
    const float *Wf2 = (const float*)d_in[24], *bf2 = (const float*)d_in[25];
    float* out = (float*)d_out;

    __half *a1, *h1, *h2, *w1t, *w2t, *w3t, *wf1t;
    float *s1p, *t1p, *s2p, *t2p;
    cudaGetSymbolAddress((void**)&a1,   g_A1);
    cudaGetSymbolAddress((void**)&h1,   g_h1);
    cudaGetSymbolAddress((void**)&h2,   g_h2);
    cudaGetSymbolAddress((void**)&w1t,  g_W1t);
    cudaGetSymbolAddress((void**)&w2t,  g_W2t);
    cudaGetSymbolAddress((void**)&w3t,  g_W3t);
    cudaGetSymbolAddress((void**)&wf1t, g_Wf1t);
    cudaGetSymbolAddress((void**)&s1p,  g_s1);
    cudaGetSymbolAddress((void**)&t1p,  g_t1);
    cudaGetSymbolAddress((void**)&s2p,  g_s2);
    cudaGetSymbolAddress((void**)&t2p,  g_t2);

    cudaFuncSetAttribute(gemm_f16, cudaFuncAttributeMaxDynamicSharedMemorySize,
                         STAGES * STAGE_BYTES);

    // prep
    prep0_kernel<<<32, 256>>>(g1, be1, m1, v1, g2, be2, m2, v2, g3, be3, m3, v3);
    prep_edge_kernel<<<E_ / 256, 256>>>(eidx, batch);
    build_a1_kernel<<<E_, 256>>>(edge_attr, arr, eidx);
    {
        dim3 gw((KP1 + 255) / 256, HP);
        prep_wt_kernel<<<gw, 256>>>(W1, KIN_, EMB_, w1t, KP1, 0);
    }
    {
        dim3 gw((HP + 255) / 256, HP);
        prep_wt_kernel<<<gw, 256>>>(W2, EMB_, EMB_, w2t, HP, 0);
        prep_wt_kernel<<<gw, 256>>>(W3, EMB_, EMB_, w3t, HP, 0);
    }
    {
        dim3 gw((HP + 255) / 256, HID_);
        prep_wt_kernel<<<gw, 256>>>(Wf1, EMB_, HID_, wf1t, HP, 1);
    }

    const int smem = STAGES * STAGE_BYTES;
    dim3 blk(128);
    dim3 grid5(5, E_ / 128);   // N=640 padded
    dim3 grid1(1, E_ / 128);

    // Layer 1: A1 @ W1t -> relu -> BN affine -> h1
    gemm_f16<<<grid5, blk, smem>>>(a1, KP1, w1t, KP1, b1, s1p, t1p,
                                   h1, HP, EMB_, KP1 / 64, 0);
    // Layer 2: h1 @ W2t -> relu -> BN affine -> h2
    gemm_f16<<<grid5, blk, smem>>>(h1, HP, w2t, HP, b2, s2p, t2p,
                                   h2, HP, EMB_, HP / 64, 0);
    // Layer 3: h2 @ W3t -> relu -> h1 (BN affine folded into Wf1t)
    gemm_f16<<<grid5, blk, smem>>>(h2, HP, w3t, HP, b3, nullptr, nullptr,
                                   h1, HP, EMB_, HP / 64, 1);
    // Pool projection: h1 @ Wf1t -> atomic segment-sum into g_gsum
    gemm_f16<<<grid1, blk, smem>>>(h1, HP, wf1t, HP, nullptr, nullptr, nullptr,
                                   nullptr, 0, HID_, HP / 64, 2);
    // Head
    head_kernel<<<G_, HID_>>>(Wf1, bf1, Wf2, bf2, out);
}

// round 7
// speedup vs baseline: 9.6849x; 1.1425x over previous
#include <cuda_runtime.h>
#include <cuda_fp16.h>
#include <cstdint>

// Problem constants
#define E_    131072
#define G_    64
#define ED_   2049
#define KIN_  2055
#define EMB_  625
#define HID_  128
#define OUT_  2
#define EPSF  1e-5f

#define KP1   2112     // padded K for layer 1 (multiple of 64)
#define HP    640      // padded N / K pitch for h buffers & weights
#define STAGES 3
#define STAGE_BYTES 32768   // A 16KB + B 16KB (128 rows x 128B, k-tile = 64 halves)

// ---------------- device scratch (allocation-free) ----------------
__device__ __half g_A1[(size_t)E_ * KP1];
__device__ __half g_h1[(size_t)E_ * HP];
__device__ __half g_h2[(size_t)E_ * HP];
__device__ __half g_W1t[HP * KP1];
__device__ __half g_W2t[HP * HP];
__device__ __half g_W3t[HP * HP];
__device__ __half g_Wf1t[HID_ * HP];
__device__ float g_s1[EMB_], g_t1[EMB_];
__device__ float g_s2[EMB_], g_t2[EMB_];
__device__ float g_s3[EMB_], g_t3[EMB_];
__device__ float g_c0[HID_];
__device__ int   g_ebatch[E_];     // batch id per edge (original order)
__device__ int   g_perm[E_];       // sorted-pos -> original edge
__device__ int   g_ebatch_s[E_];   // batch id per sorted pos
__device__ int   g_bcnt[G_];
__device__ int   g_bpos[G_];
__device__ float g_cnt[G_];
__device__ float g_gsum[G_ * HID_];

// ---------------- helpers ----------------
__device__ __forceinline__ uint32_t smem_u32(const void* p) {
    return (uint32_t)__cvta_generic_to_shared(p);
}
__device__ __forceinline__ void cp16(uint32_t dst, const void* src) {
    asm volatile("cp.async.cg.shared.global [%0], [%1], 16;\n" :: "r"(dst), "l"(src));
}
#define CP_COMMIT() asm volatile("cp.async.commit_group;\n" ::: "memory")
#define CP_WAIT2()  asm volatile("cp.async.wait_group 2;\n" ::: "memory")

__device__ __forceinline__ void ldsm4(uint32_t& r0, uint32_t& r1, uint32_t& r2, uint32_t& r3,
                                      uint32_t addr) {
    asm volatile("ldmatrix.sync.aligned.m8n8.x4.shared.b16 {%0,%1,%2,%3}, [%4];"
                 : "=r"(r0), "=r"(r1), "=r"(r2), "=r"(r3) : "r"(addr));
}

#define MMA_F16(d, a, b0, b1)                                           \
    asm volatile(                                                       \
        "mma.sync.aligned.m16n8k16.row.col.f32.f16.f16.f32 "            \
        "{%0,%1,%2,%3}, {%4,%5,%6,%7}, {%8,%9}, {%0,%1,%2,%3};"         \
        : "+f"(d[0]), "+f"(d[1]), "+f"(d[2]), "+f"(d[3])                \
        : "r"(a[0]), "r"(a[1]), "r"(a[2]), "r"(a[3]), "r"(b0), "r"(b1))

// ---------------- prep kernels ----------------
__global__ void prep0_kernel(const float* __restrict__ g1, const float* __restrict__ be1,
                             const float* __restrict__ m1, const float* __restrict__ v1,
                             const float* __restrict__ g2, const float* __restrict__ be2,
                             const float* __restrict__ m2, const float* __restrict__ v2,
                             const float* __restrict__ g3, const float* __restrict__ be3,
                             const float* __restrict__ m3, const float* __restrict__ v3)
{
    int i = blockIdx.x * blockDim.x + threadIdx.x;
    if (i < EMB_) {
        float s1 = g1[i] / sqrtf(v1[i] + EPSF);
        g_s1[i] = s1; g_t1[i] = be1[i] - m1[i] * s1;
        float s2 = g2[i] / sqrtf(v2[i] + EPSF);
        g_s2[i] = s2; g_t2[i] = be2[i] - m2[i] * s2;
        float s3 = g3[i] / sqrtf(v3[i] + EPSF);
        g_s3[i] = s3; g_t3[i] = be3[i] - m3[i] * s3;
    }
    if (i < G_) g_bcnt[i] = 0;
    if (i < G_ * HID_) g_gsum[i] = 0.0f;
}

__global__ void prep_edge_kernel(const int* __restrict__ eidx,
                                 const int* __restrict__ batch)
{
    __shared__ int hist[G_];
    int t = threadIdx.x;
    if (t < G_) hist[t] = 0;
    __syncthreads();
    int e = blockIdx.x * blockDim.x + t;
    int b = batch[eidx[e]];
    g_ebatch[e] = b;
    atomicAdd(&hist[b], 1);
    __syncthreads();
    if (t < G_) atomicAdd(&g_bcnt[t], hist[t]);
}

__global__ void prep_prefix_kernel()   // 1 block, 64 threads
{
    __shared__ int s[G_];
    int t = threadIdx.x;
    int c = g_bcnt[t];
    s[t] = c;
    __syncthreads();
    int off = 0;
    for (int i = 0; i < t; i++) off += s[i];
    g_bpos[t] = off;
    g_cnt[t] = (float)c;
}

__global__ void scatter_kernel()
{
    int e = blockIdx.x * blockDim.x + threadIdx.x;
    int b = g_ebatch[e];
    int pos = atomicAdd(&g_bpos[b], 1);
    g_perm[pos] = e;
    g_ebatch_s[pos] = b;
}

// Build fp16 concatenated A1[e][0..KP1), vectorized stores (uint2 = 4 halves)
__global__ void build_a1_kernel(const float* __restrict__ ea,
                                const float* __restrict__ arr,
                                const int* __restrict__ eidx)
{
    const int e = blockIdx.x;
    const float* src = ea + (size_t)e * ED_;
    __half* dst = g_A1 + (size_t)e * KP1;
    const int t = threadIdx.x;

    // k in [0, 2048): 512 groups of 4
    for (int q = t; q < 512; q += blockDim.x) {
        int k = q * 4;
        float f0 = src[k], f1 = src[k + 1], f2 = src[k + 2], f3 = src[k + 3];
        __half2 p0 = __floats2half2_rn(f0, f1);
        __half2 p1 = __floats2half2_rn(f2, f3);
        uint2 u;
        u.x = *(uint32_t*)&p0;
        u.y = *(uint32_t*)&p1;
        *(uint2*)(dst + k) = u;
    }
    // tail: k in [2048, 2112)
    if (t < 64) {
        int k = 2048 + t;
        float v;
        if (k < ED_) {
            v = src[k];
        } else if (k < ED_ + 3) {
            v = arr[3 * eidx[e] + (k - ED_)];
        } else if (k < ED_ + 6) {
            v = arr[3 * eidx[E_ + e] + (k - ED_ - 3)];
        } else {
            v = 0.0f;
        }
        dst[k] = __float2half_rn(v);
    }
}

// Wt[n][k] = fp16( W[k][n] * (scale_k ? s3[k] : 1) ), zero-padded to [NP][KP]
__global__ void prep_wt_kernel(const float* __restrict__ W, int K, int N,
                               __half* __restrict__ Wt, int KP, int scale_k)
{
    int k = blockIdx.x * blockDim.x + threadIdx.x;
    int n = blockIdx.y;
    if (k >= KP) return;
    float v = 0.0f;
    if (k < K && n < N) {
        v = W[(size_t)k * N + n];
        if (scale_k) v *= g_s3[k];
    }
    Wt[(size_t)n * KP + k] = __float2half_rn(v);
}

// c0[n] = t3 @ Wf1[:, n]  (constant from layer-3 BN fold), computed once
__global__ void prep_c0_kernel(const float* __restrict__ Wf1)
{
    int n = threadIdx.x;
    float c0 = 0.0f;
    for (int k = 0; k < EMB_; k++) c0 = fmaf(g_t3[k], Wf1[k * HID_ + n], c0);
    g_c0[n] = c0;
}

// ---------------- fp16 tensor-core GEMM: cp.async pipeline + ldmatrix ----------------
//   emode 0: h = max(z + bias, 0) * scale + shift  -> fp16 store (0 for n >= Nreal)
//   emode 1: h = max(z + bias, 0)                  -> fp16 store
//   emode 2: rows gathered via g_perm (sorted by batch); segment-sum into g_gsum
__global__ __launch_bounds__(128)
void gemm_f16(const __half* __restrict__ A, int lda,
              const __half* __restrict__ Bt, int ldbt,
              const float* __restrict__ bias,
              const float* __restrict__ scale,
              const float* __restrict__ shift,
              __half* __restrict__ C, int ldc,
              int Nreal, int ktiles, int emode)
{
    extern __shared__ __align__(16) char smem_raw[];
    const uint32_t sb = smem_u32(smem_raw);

    const int tid  = threadIdx.x;
    const int lane = tid & 31;
    const int w    = tid >> 5;            // 0..3
    const int wm   = (w & 1) * 64;
    const int wn   = (w >> 1) * 64;
    const int row0 = blockIdx.y * 128;
    const int col0 = blockIdx.x * 128;

    const __half* Abase = A  + (size_t)row0 * lda;
    const __half* Bbase = Bt + (size_t)col0 * ldbt;

    // per-thread gathered row pointers for pool GEMM (constant across ktiles)
    const __half* arow[8];
    if (emode == 2) {
#pragma unroll
        for (int i = 0; i < 8; i++) {
            int m = (i * 128 + tid) >> 3;
            arow[i] = A + (size_t)g_perm[row0 + m] * lda;
        }
    }

    // ldmatrix lane address components
    const int rA  = wm + (lane & 15);
    const int hiA = lane >> 4;
    const int xa  = rA & 7;
    const int rB  = wn + ((lane >> 4) & 1) * 8 + (lane & 7);
    const int hiB = (lane >> 3) & 1;
    const int xb  = rB & 7;

    float acc[4][8][4];
#pragma unroll
    for (int mi = 0; mi < 4; mi++)
#pragma unroll
        for (int ni = 0; ni < 8; ni++)
#pragma unroll
            for (int c = 0; c < 4; c++) acc[mi][ni][c] = 0.0f;

    auto stage = [&](int s, int kt) {
        uint32_t sA = sb + s * STAGE_BYTES;
        uint32_t sB = sA + 16384;
        const __half* Ak = Abase + kt * 64;
        const __half* Bk = Bbase + kt * 64;
#pragma unroll
        for (int i = 0; i < 8; i++) {
            int id = i * 128 + tid;
            int m  = id >> 3;
            int c  = id & 7;
            const __half* srcA = (emode == 2) ? (arow[i] + kt * 64 + c * 8)
                                              : (Ak + (size_t)m * lda + c * 8);
            cp16(sA + m * 128 + ((c ^ (m & 7)) << 4), srcA);
        }
#pragma unroll
        for (int i = 0; i < 8; i++) {
            int id = i * 128 + tid;
            int n  = id >> 3;
            int c  = id & 7;
            cp16(sB + n * 128 + ((c ^ (n & 7)) << 4), Bk + (size_t)n * ldbt + c * 8);
        }
    };

#pragma unroll
    for (int s = 0; s < STAGES - 1; s++) {
        if (s < ktiles) stage(s, s);
        CP_COMMIT();
    }

    for (int kt = 0; kt < ktiles; kt++) {
        int pf = kt + STAGES - 1;
        if (pf < ktiles) stage(pf % STAGES, pf);
        CP_COMMIT();
        CP_WAIT2();
        __syncthreads();

        const int s = kt % STAGES;
        const uint32_t sA = sb + s * STAGE_BYTES;
        const uint32_t sB = sA + 16384;

#pragma unroll
        for (int k16 = 0; k16 < 4; k16++) {
            uint32_t a[4][4];
#pragma unroll
            for (int mi = 0; mi < 4; mi++) {
                uint32_t addr = sA + (rA + mi * 16) * 128
                              + ((uint32_t)((k16 * 2 + hiA) ^ xa) << 4);
                ldsm4(a[mi][0], a[mi][1], a[mi][2], a[mi][3], addr);
            }
            uint32_t bf[4][4];
#pragma unroll
            for (int nj = 0; nj < 4; nj++) {
                uint32_t addr = sB + (rB + nj * 16) * 128
                              + ((uint32_t)((k16 * 2 + hiB) ^ xb) << 4);
                ldsm4(bf[nj][0], bf[nj][1], bf[nj][2], bf[nj][3], addr);
            }
#pragma unroll
            for (int mi = 0; mi < 4; mi++) {
#pragma unroll
                for (int nj = 0; nj < 4; nj++) {
                    MMA_F16(acc[mi][2 * nj],     a[mi], bf[nj][0], bf[nj][1]);
                    MMA_F16(acc[mi][2 * nj + 1], a[mi], bf[nj][2], bf[nj][3]);
                }
            }
        }
        __syncthreads();
    }

    // ---- epilogue ----
    const int g  = lane >> 2;
    const int tg = lane & 3;
    if (emode == 2) {
        const int b0 = g_ebatch_s[row0];
        const int bL = g_ebatch_s[row0 + 127];
        if (b0 == bL) {
            // uniform tile: reduce all 128 rows, 128 atomics total
            float s[8][2];
#pragma unroll
            for (int ni = 0; ni < 8; ni++) {
                s[ni][0] = 0.0f; s[ni][1] = 0.0f;
#pragma unroll
                for (int mi = 0; mi < 4; mi++) {
                    s[ni][0] += acc[mi][ni][0] + acc[mi][ni][2];
                    s[ni][1] += acc[mi][ni][1] + acc[mi][ni][3];
                }
            }
#pragma unroll
            for (int off = 4; off <= 16; off <<= 1) {
#pragma unroll
                for (int ni = 0; ni < 8; ni++) {
                    s[ni][0] += __shfl_xor_sync(0xffffffffu, s[ni][0], off);
                    s[ni][1] += __shfl_xor_sync(0xffffffffu, s[ni][1], off);
                }
            }
            __shared__ float red[2][128];
            if (lane < 4) {
#pragma unroll
                for (int ni = 0; ni < 8; ni++) {
                    red[wm >> 6][wn + ni * 8 + lane * 2 + 0] = s[ni][0];
                    red[wm >> 6][wn + ni * 8 + lane * 2 + 1] = s[ni][1];
                }
            }
            __syncthreads();
            atomicAdd(&g_gsum[b0 * HID_ + tid], red[0][tid] + red[1][tid]);
        } else {
            // mixed tile (rare): per-row atomics
#pragma unroll
            for (int mi = 0; mi < 4; mi++) {
                int r_lo = row0 + wm + mi * 16 + g;
                int b_lo = g_ebatch_s[r_lo];
                int b_hi = g_ebatch_s[r_lo + 8];
#pragma unroll
                for (int ni = 0; ni < 8; ni++) {
                    int cc = wn + ni * 8 + tg * 2;
                    atomicAdd(&g_gsum[b_lo * HID_ + cc],     acc[mi][ni][0]);
                    atomicAdd(&g_gsum[b_lo * HID_ + cc + 1], acc[mi][ni][1]);
                    atomicAdd(&g_gsum[b_hi * HID_ + cc],     acc[mi][ni][2]);
                    atomicAdd(&g_gsum[b_hi * HID_ + cc + 1], acc[mi][ni][3]);
                }
            }
        }
    } else {
#pragma unroll
        for (int mi = 0; mi < 4; mi++) {
            int r_lo = row0 + wm + mi * 16 + g;
            __half* crow_lo = C + (size_t)r_lo * ldc;
            __half* crow_hi = crow_lo + (size_t)8 * ldc;
#pragma unroll
            for (int ni = 0; ni < 8; ni++) {
                int cc = col0 + wn + ni * 8 + tg * 2;
                float z0 = 0.0f, z1 = 0.0f, z2 = 0.0f, z3 = 0.0f;
                if (cc < Nreal) {
                    float b0 = bias[cc];
                    z0 = fmaxf(acc[mi][ni][0] + b0, 0.0f);
                    z2 = fmaxf(acc[mi][ni][2] + b0, 0.0f);
                    if (emode == 0) {
                        float sc0 = scale[cc], sh0 = shift[cc];
                        z0 = z0 * sc0 + sh0;  z2 = z2 * sc0 + sh0;
                    }
                }
                if (cc + 1 < Nreal) {
                    float b1 = bias[cc + 1];
                    z1 = fmaxf(acc[mi][ni][1] + b1, 0.0f);
                    z3 = fmaxf(acc[mi][ni][3] + b1, 0.0f);
                    if (emode == 0) {
                        float sc1 = scale[cc + 1], sh1 = shift[cc + 1];
                        z1 = z1 * sc1 + sh1;  z3 = z3 * sc1 + sh1;
                    }
                }
                *(__half2*)&crow_lo[cc] = __floats2half2_rn(z0, z1);
                *(__half2*)&crow_hi[cc] = __floats2half2_rn(z2, z3);
            }
        }
    }
}

// ---------------- head: mean + 2-layer MLP ----------------
__global__ void head_kernel(const float* __restrict__ bf1,
                            const float* __restrict__ Wf2,
                            const float* __restrict__ bf2,
                            float* __restrict__ out)
{
    const int g = blockIdx.x;
    const int n = threadIdx.x;
    float cnt = g_cnt[g];
    float v = (cnt > 0.0f) ? (g_gsum[g * HID_ + n] / cnt + g_c0[n]) : 0.0f;
    float h = fmaxf(v + bf1[n], 0.0f);

    __shared__ float s0[HID_], s1[HID_];
    s0[n] = h * Wf2[n * OUT_ + 0];
    s1[n] = h * Wf2[n * OUT_ + 1];
    __syncthreads();
    for (int off = HID_ / 2; off > 0; off >>= 1) {
        if (n < off) { s0[n] += s0[n + off]; s1[n] += s1[n + off]; }
        __syncthreads();
    }
    if (n == 0) {
        out[g * OUT_ + 0] = s0[0] + bf2[0];
        out[g * OUT_ + 1] = s1[0] + bf2[1];
    }
}

// ---------------- launch ----------------
extern "C" void kernel_launch(void* const* d_in, const int* in_sizes, int n_in,
                              void* d_out, int out_size)
{
    (void)in_sizes; (void)n_in; (void)out_size;

    const float* edge_attr = (const float*)d_in[0];
    const float* arr       = (const float*)d_in[1];
    const int*   eidx      = (const int*)d_in[2];
    const int*   batch     = (const int*)d_in[3];
    const float *W1 = (const float*)d_in[4],  *b1 = (const float*)d_in[5];
    const float *g1 = (const float*)d_in[6],  *be1 = (const float*)d_in[7];
    const float *m1 = (const float*)d_in[8],  *v1 = (const float*)d_in[9];
    const float *W2 = (const float*)d_in[10], *b2 = (const float*)d_in[11];
    const float *g2 = (const float*)d_in[12], *be2 = (const float*)d_in[13];
    const float *m2 = (const float*)d_in[14], *v2 = (const float*)d_in[15];
    const float *W3 = (const float*)d_in[16], *b3 = (const float*)d_in[17];
    const float *g3 = (const float*)d_in[18], *be3 = (const float*)d_in[19];
    const float *m3 = (const float*)d_in[20], *v3 = (const float*)d_in[21];
    const float *Wf1 = (const float*)d_in[22], *bf1 = (const float*)d_in[23];
    const float *Wf2 = (const float*)d_in[24], *bf2 = (const float*)d_in[25];
    float* out = (float*)d_out;

    __half *a1, *h1, *h2, *w1t, *w2t, *w3t, *wf1t;
    float *s1p, *t1p, *s2p, *t2p;
    cudaGetSymbolAddress((void**)&a1,   g_A1);
    cudaGetSymbolAddress((void**)&h1,   g_h1);
    cudaGetSymbolAddress((void**)&h2,   g_h2);
    cudaGetSymbolAddress((void**)&w1t,  g_W1t);
    cudaGetSymbolAddress((void**)&w2t,  g_W2t);
    cudaGetSymbolAddress((void**)&w3t,  g_W3t);
    cudaGetSymbolAddress((void**)&wf1t, g_Wf1t);
    cudaGetSymbolAddress((void**)&s1p,  g_s1);
    cudaGetSymbolAddress((void**)&t1p,  g_t1);
    cudaGetSymbolAddress((void**)&s2p,  g_s2);
    cudaGetSymbolAddress((void**)&t2p,  g_t2);

    cudaFuncSetAttribute(gemm_f16, cudaFuncAttributeMaxDynamicSharedMemorySize,
                         STAGES * STAGE_BYTES);

    // prep
    prep0_kernel<<<32, 256>>>(g1, be1, m1, v1, g2, be2, m2, v2, g3, be3, m3, v3);
    prep_edge_kernel<<<E_ / 256, 256>>>(eidx, batch);
    prep_prefix_kernel<<<1, G_>>>();
    scatter_kernel<<<E_ / 256, 256>>>();
    build_a1_kernel<<<E_, 256>>>(edge_attr, arr, eidx);
    {
        dim3 gw((KP1 + 255) / 256, HP);
        prep_wt_kernel<<<gw, 256>>>(W1, KIN_, EMB_, w1t, KP1, 0);
    }
    {
        dim3 gw((HP + 255) / 256, HP);
        prep_wt_kernel<<<gw, 256>>>(W2, EMB_, EMB_, w2t, HP, 0);
        prep_wt_kernel<<<gw, 256>>>(W3, EMB_, EMB_, w3t, HP, 0);
    }
    {
        dim3 gw((HP + 255) / 256, HID_);
        prep_wt_kernel<<<gw, 256>>>(Wf1, EMB_, HID_, wf1t, HP, 1);
    }
    prep_c0_kernel<<<1, HID_>>>(Wf1);

    const int smem = STAGES * STAGE_BYTES;
    dim3 blk(128);
    dim3 grid5(5, E_ / 128);   // N=640 padded
    dim3 grid1(1, E_ / 128);

    // Layer 1: A1 @ W1t -> relu -> BN affine -> h1
    gemm_f16<<<grid5, blk, smem>>>(a1, KP1, w1t, KP1, b1, s1p, t1p,
                                   h1, HP, EMB_, KP1 / 64, 0);
    // Layer 2: h1 @ W2t -> relu -> BN affine -> h2
    gemm_f16<<<grid5, blk, smem>>>(h1, HP, w2t, HP, b2, s2p, t2p,
                                   h2, HP, EMB_, HP / 64, 0);
    // Layer 3: h2 @ W3t -> relu -> h1 (BN affine folded into Wf1t)
    gemm_f16<<<grid5, blk, smem>>>(h2, HP, w3t, HP, b3, nullptr, nullptr,
                                   h1, HP, EMB_, HP / 64, 1);
    // Pool projection: gathered (sorted) h1 rows @ Wf1t -> segment-sum into g_gsum
    gemm_f16<<<grid1, blk, smem>>>(h1, HP, wf1t, HP, nullptr, nullptr, nullptr,
                                   nullptr, 0, HID_, HP / 64, 2);
    // Head
    head_kernel<<<G_, HID_>>>(bf1, Wf2, bf2, out);
}

// round 8
// speedup vs baseline: 9.6935x; 1.0009x over previous
#include <cuda_runtime.h>
#include <cuda_fp16.h>
#include <cstdint>

// Problem constants
#define E_    131072
#define G_    64
#define ED_   2049
#define KIN_  2055
#define EMB_  625
#define HID_  128
#define OUT_  2
#define EPSF  1e-5f

#define KP1   2112     // padded K for layer 1 (multiple of 64)
#define HP    640      // padded N / K pitch for h buffers & weights
#define STAGES 3
#define STAGE_BYTES 32768   // A 16KB + B 16KB (128 rows x 128B, k-tile = 64 halves)

// ---------------- device scratch (allocation-free) ----------------
__device__ __half g_A1[(size_t)E_ * KP1];
__device__ __half g_h1[(size_t)E_ * HP];
__device__ __half g_h2[(size_t)E_ * HP];
__device__ __half g_W1t[HP * KP1];
__device__ __half g_W2t[HP * HP];
__device__ __half g_W3t[HP * HP];
__device__ __half g_Wf1t[HID_ * HP];
__device__ float g_s1[EMB_], g_t1[EMB_];
__device__ float g_s2[EMB_], g_t2[EMB_];
__device__ float g_s3[EMB_], g_t3[EMB_];
__device__ float g_c0[HID_];
__device__ int   g_ebatch[E_];     // batch id per edge (original order)
__device__ int   g_perm[E_];       // sorted-pos -> original edge
__device__ int   g_ebatch_s[E_];   // batch id per sorted pos
__device__ int   g_bcnt[G_];
__device__ int   g_bpos[G_];
__device__ float g_cnt[G_];
__device__ float g_gsum[G_ * HID_];

// ---------------- helpers ----------------
__device__ __forceinline__ uint32_t smem_u32(const void* p) {
    return (uint32_t)__cvta_generic_to_shared(p);
}
__device__ __forceinline__ void cp16(uint32_t dst, const void* src) {
    asm volatile("cp.async.cg.shared.global [%0], [%1], 16;\n" :: "r"(dst), "l"(src));
}
#define CP_COMMIT() asm volatile("cp.async.commit_group;\n" ::: "memory")
#define CP_WAIT2()  asm volatile("cp.async.wait_group 2;\n" ::: "memory")

__device__ __forceinline__ void ldsm4(uint32_t& r0, uint32_t& r1, uint32_t& r2, uint32_t& r3,
                                      uint32_t addr) {
    asm volatile("ldmatrix.sync.aligned.m8n8.x4.shared.b16 {%0,%1,%2,%3}, [%4];"
                 : "=r"(r0), "=r"(r1), "=r"(r2), "=r"(r3) : "r"(addr));
}

#define MMA_F16(d, a, b0, b1)                                           \
    asm volatile(                                                       \
        "mma.sync.aligned.m16n8k16.row.col.f32.f16.f16.f32 "            \
        "{%0,%1,%2,%3}, {%4,%5,%6,%7}, {%8,%9}, {%0,%1,%2,%3};"         \
        : "+f"(d[0]), "+f"(d[1]), "+f"(d[2]), "+f"(d[3])                \
        : "r"(a[0]), "r"(a[1]), "r"(a[2]), "r"(a[3]), "r"(b0), "r"(b1))

// ---------------- prep kernels ----------------
__global__ void prep0_kernel(const float* __restrict__ g1, const float* __restrict__ be1,
                             const float* __restrict__ m1, const float* __restrict__ v1,
                             const float* __restrict__ g2, const float* __restrict__ be2,
                             const float* __restrict__ m2, const float* __restrict__ v2,
                             const float* __restrict__ g3, const float* __restrict__ be3,
                             const float* __restrict__ m3, const float* __restrict__ v3)
{
    int i = blockIdx.x * blockDim.x + threadIdx.x;
    if (i < EMB_) {
        float s1 = g1[i] / sqrtf(v1[i] + EPSF);
        g_s1[i] = s1; g_t1[i] = be1[i] - m1[i] * s1;
        float s2 = g2[i] / sqrtf(v2[i] + EPSF);
        g_s2[i] = s2; g_t2[i] = be2[i] - m2[i] * s2;
        float s3 = g3[i] / sqrtf(v3[i] + EPSF);
        g_s3[i] = s3; g_t3[i] = be3[i] - m3[i] * s3;
    }
    if (i < G_) g_bcnt[i] = 0;
    if (i < G_ * HID_) g_gsum[i] = 0.0f;
}

__global__ void prep_edge_kernel(const int* __restrict__ eidx,
                                 const int* __restrict__ batch)
{
    __shared__ int hist[G_];
    int t = threadIdx.x;
    if (t < G_) hist[t] = 0;
    __syncthreads();
    int e = blockIdx.x * blockDim.x + t;
    int b = batch[eidx[e]];
    g_ebatch[e] = b;
    atomicAdd(&hist[b], 1);
    __syncthreads();
    if (t < G_) atomicAdd(&g_bcnt[t], hist[t]);
}

__global__ void prep_prefix_kernel()   // 1 block, 64 threads
{
    __shared__ int s[G_];
    int t = threadIdx.x;
    int c = g_bcnt[t];
    s[t] = c;
    __syncthreads();
    int off = 0;
    for (int i = 0; i < t; i++) off += s[i];
    g_bpos[t] = off;
    g_cnt[t] = (float)c;
}

__global__ void scatter_kernel()
{
    int e = blockIdx.x * blockDim.x + threadIdx.x;
    int b = g_ebatch[e];
    int pos = atomicAdd(&g_bpos[b], 1);
    g_perm[pos] = e;
    g_ebatch_s[pos] = b;
}

// Build fp16 concatenated A1[e][0..KP1), vectorized stores (uint2 = 4 halves)
__global__ void build_a1_kernel(const float* __restrict__ ea,
                                const float* __restrict__ arr,
                                const int* __restrict__ eidx)
{
    const int e = blockIdx.x;
    const float* src = ea + (size_t)e * ED_;
    __half* dst = g_A1 + (size_t)e * KP1;
    const int t = threadIdx.x;

    // k in [0, 2048): 512 groups of 4
    for (int q = t; q < 512; q += blockDim.x) {
        int k = q * 4;
        float f0 = src[k], f1 = src[k + 1], f2 = src[k + 2], f3 = src[k + 3];
        __half2 p0 = __floats2half2_rn(f0, f1);
        __half2 p1 = __floats2half2_rn(f2, f3);
        uint2 u;
        u.x = *(uint32_t*)&p0;
        u.y = *(uint32_t*)&p1;
        *(uint2*)(dst + k) = u;
    }
    // tail: k in [2048, 2112)
    if (t < 64) {
        int k = 2048 + t;
        float v;
        if (k < ED_) {
            v = src[k];
        } else if (k < ED_ + 3) {
            v = arr[3 * eidx[e] + (k - ED_)];
        } else if (k < ED_ + 6) {
            v = arr[3 * eidx[E_ + e] + (k - ED_ - 3)];
        } else {
            v = 0.0f;
        }
        dst[k] = __float2half_rn(v);
    }
}

// Wt[n][k] = fp16( W[k][n] * (scale_k ? s3[k] : 1) ), zero-padded to [NP][KP]
__global__ void prep_wt_kernel(const float* __restrict__ W, int K, int N,
                               __half* __restrict__ Wt, int KP, int scale_k)
{
    int k = blockIdx.x * blockDim.x + threadIdx.x;
    int n = blockIdx.y;
    if (k >= KP) return;
    float v = 0.0f;
    if (k < K && n < N) {
        v = W[(size_t)k * N + n];
        if (scale_k) v *= g_s3[k];
    }
    Wt[(size_t)n * KP + k] = __float2half_rn(v);
}

// c0[n] = t3 @ Wf1[:, n]  (constant from layer-3 BN fold), computed once
__global__ void prep_c0_kernel(const float* __restrict__ Wf1)
{
    int n = threadIdx.x;
    float c0 = 0.0f;
    for (int k = 0; k < EMB_; k++) c0 = fmaf(g_t3[k], Wf1[k * HID_ + n], c0);
    g_c0[n] = c0;
}

// ---------------- fp16 tensor-core GEMM: cp.async pipeline + ldmatrix ----------------
//   emode 0: h = max(z + bias, 0) * scale + shift  -> fp16 store (0 for n >= Nreal)
//   emode 1: h = max(z + bias, 0)                  -> fp16 store
//   emode 2: rows gathered via g_perm (sorted by batch); segment-sum into g_gsum
__global__ __launch_bounds__(128)
void gemm_f16(const __half* __restrict__ A, int lda,
              const __half* __restrict__ Bt, int ldbt,
              const float* __restrict__ bias,
              const float* __restrict__ scale,
              const float* __restrict__ shift,
              __half* __restrict__ C, int ldc,
              int Nreal, int ktiles, int emode)
{
    extern __shared__ __align__(16) char smem_raw[];
    const uint32_t sb = smem_u32(smem_raw);

    const int tid  = threadIdx.x;
    const int lane = tid & 31;
    const int w    = tid >> 5;            // 0..3
    const int wm   = (w & 1) * 64;
    const int wn   = (w >> 1) * 64;
    const int row0 = blockIdx.y * 128;
    const int col0 = blockIdx.x * 128;

    const __half* Abase = A  + (size_t)row0 * lda;
    const __half* Bbase = Bt + (size_t)col0 * ldbt;

    // per-thread gathered row pointers for pool GEMM (constant across ktiles)
    const __half* arow[8];
    if (emode == 2) {
#pragma unroll
        for (int i = 0; i < 8; i++) {
            int m = (i * 128 + tid) >> 3;
            arow[i] = A + (size_t)g_perm[row0 + m] * lda;
        }
    }

    // ldmatrix lane address components
    const int rA  = wm + (lane & 15);
    const int hiA = lane >> 4;
    const int xa  = rA & 7;
    const int rB  = wn + ((lane >> 4) & 1) * 8 + (lane & 7);
    const int hiB = (lane >> 3) & 1;
    const int xb  = rB & 7;

    float acc[4][8][4];
#pragma unroll
    for (int mi = 0; mi < 4; mi++)
#pragma unroll
        for (int ni = 0; ni < 8; ni++)
#pragma unroll
            for (int c = 0; c < 4; c++) acc[mi][ni][c] = 0.0f;

    auto stage = [&](int s, int kt) {
        uint32_t sA = sb + s * STAGE_BYTES;
        uint32_t sB = sA + 16384;
        const __half* Ak = Abase + kt * 64;
        const __half* Bk = Bbase + kt * 64;
#pragma unroll
        for (int i = 0; i < 8; i++) {
            int id = i * 128 + tid;
            int m  = id >> 3;
            int c  = id & 7;
            const __half* srcA = (emode == 2) ? (arow[i] + kt * 64 + c * 8)
                                              : (Ak + (size_t)m * lda + c * 8);
            cp16(sA + m * 128 + ((c ^ (m & 7)) << 4), srcA);
        }
#pragma unroll
        for (int i = 0; i < 8; i++) {
            int id = i * 128 + tid;
            int n  = id >> 3;
            int c  = id & 7;
            cp16(sB + n * 128 + ((c ^ (n & 7)) << 4), Bk + (size_t)n * ldbt + c * 8);
        }
    };

#pragma unroll
    for (int s = 0; s < STAGES - 1; s++) {
        if (s < ktiles) stage(s, s);
        CP_COMMIT();
    }

    for (int kt = 0; kt < ktiles; kt++) {
        int pf = kt + STAGES - 1;
        if (pf < ktiles) stage(pf % STAGES, pf);
        CP_COMMIT();
        CP_WAIT2();
        __syncthreads();

        const int s = kt % STAGES;
        const uint32_t sA = sb + s * STAGE_BYTES;
        const uint32_t sB = sA + 16384;

#pragma unroll
        for (int k16 = 0; k16 < 4; k16++) {
            uint32_t a[4][4];
#pragma unroll
            for (int mi = 0; mi < 4; mi++) {
                uint32_t addr = sA + (rA + mi * 16) * 128
                              + ((uint32_t)((k16 * 2 + hiA) ^ xa) << 4);
                ldsm4(a[mi][0], a[mi][1], a[mi][2], a[mi][3], addr);
            }
            uint32_t bf[4][4];
#pragma unroll
            for (int nj = 0; nj < 4; nj++) {
                uint32_t addr = sB + (rB + nj * 16) * 128
                              + ((uint32_t)((k16 * 2 + hiB) ^ xb) << 4);
                ldsm4(bf[nj][0], bf[nj][1], bf[nj][2], bf[nj][3], addr);
            }
#pragma unroll
            for (int mi = 0; mi < 4; mi++) {
#pragma unroll
                for (int nj = 0; nj < 4; nj++) {
                    MMA_F16(acc[mi][2 * nj],     a[mi], bf[nj][0], bf[nj][1]);
                    MMA_F16(acc[mi][2 * nj + 1], a[mi], bf[nj][2], bf[nj][3]);
                }
            }
        }
        __syncthreads();
    }

    // ---- epilogue ----
    const int g  = lane >> 2;
    const int tg = lane & 3;
    if (emode == 2) {
        const int b0 = g_ebatch_s[row0];
        const int bL = g_ebatch_s[row0 + 127];
        if (b0 == bL) {
            // uniform tile: reduce all 128 rows, 128 atomics total
            float s[8][2];
#pragma unroll
            for (int ni = 0; ni < 8; ni++) {
                s[ni][0] = 0.0f; s[ni][1] = 0.0f;
#pragma unroll
                for (int mi = 0; mi < 4; mi++) {
                    s[ni][0] += acc[mi][ni][0] + acc[mi][ni][2];
                    s[ni][1] += acc[mi][ni][1] + acc[mi][ni][3];
                }
            }
#pragma unroll
            for (int off = 4; off <= 16; off <<= 1) {
#pragma unroll
                for (int ni = 0; ni < 8; ni++) {
                    s[ni][0] += __shfl_xor_sync(0xffffffffu, s[ni][0], off);
                    s[ni][1] += __shfl_xor_sync(0xffffffffu, s[ni][1], off);
                }
            }
            __shared__ float red[2][128];
            if (lane < 4) {
#pragma unroll
                for (int ni = 0; ni < 8; ni++) {
                    red[wm >> 6][wn + ni * 8 + lane * 2 + 0] = s[ni][0];
                    red[wm >> 6][wn + ni * 8 + lane * 2 + 1] = s[ni][1];
                }
            }
            __syncthreads();
            atomicAdd(&g_gsum[b0 * HID_ + tid], red[0][tid] + red[1][tid]);
        } else {
            // mixed tile (rare): per-row atomics
#pragma unroll
            for (int mi = 0; mi < 4; mi++) {
                int r_lo = row0 + wm + mi * 16 + g;
                int b_lo = g_ebatch_s[r_lo];
                int b_hi = g_ebatch_s[r_lo + 8];
#pragma unroll
                for (int ni = 0; ni < 8; ni++) {
                    int cc = wn + ni * 8 + tg * 2;
                    atomicAdd(&g_gsum[b_lo * HID_ + cc],     acc[mi][ni][0]);
                    atomicAdd(&g_gsum[b_lo * HID_ + cc + 1], acc[mi][ni][1]);
                    atomicAdd(&g_gsum[b_hi * HID_ + cc],     acc[mi][ni][2]);
                    atomicAdd(&g_gsum[b_hi * HID_ + cc + 1], acc[mi][ni][3]);
                }
            }
        }
    } else {
#pragma unroll
        for (int mi = 0; mi < 4; mi++) {
            int r_lo = row0 + wm + mi * 16 + g;
            __half* crow_lo = C + (size_t)r_lo * ldc;
            __half* crow_hi = crow_lo + (size_t)8 * ldc;
#pragma unroll
            for (int ni = 0; ni < 8; ni++) {
                int cc = col0 + wn + ni * 8 + tg * 2;
                float z0 = 0.0f, z1 = 0.0f, z2 = 0.0f, z3 = 0.0f;
                if (cc < Nreal) {
                    float b0 = bias[cc];
                    z0 = fmaxf(acc[mi][ni][0] + b0, 0.0f);
                    z2 = fmaxf(acc[mi][ni][2] + b0, 0.0f);
                    if (emode == 0) {
                        float sc0 = scale[cc], sh0 = shift[cc];
                        z0 = z0 * sc0 + sh0;  z2 = z2 * sc0 + sh0;
                    }
                }
                if (cc + 1 < Nreal) {
                    float b1 = bias[cc + 1];
                    z1 = fmaxf(acc[mi][ni][1] + b1, 0.0f);
                    z3 = fmaxf(acc[mi][ni][3] + b1, 0.0f);
                    if (emode == 0) {
                        float sc1 = scale[cc + 1], sh1 = shift[cc + 1];
                        z1 = z1 * sc1 + sh1;  z3 = z3 * sc1 + sh1;
                    }
                }
                *(__half2*)&crow_lo[cc] = __floats2half2_rn(z0, z1);
                *(__half2*)&crow_hi[cc] = __floats2half2_rn(z2, z3);
            }
        }
    }
}

// ---------------- head: mean + 2-layer MLP ----------------
__global__ void head_kernel(const float* __restrict__ bf1,
                            const float* __restrict__ Wf2,
                            const float* __restrict__ bf2,
                            float* __restrict__ out)
{
    const int g = blockIdx.x;
    const int n = threadIdx.x;
    float cnt = g_cnt[g];
    float v = (cnt > 0.0f) ? (g_gsum[g * HID_ + n] / cnt + g_c0[n]) : 0.0f;
    float h = fmaxf(v + bf1[n], 0.0f);

    __shared__ float s0[HID_], s1[HID_];
    s0[n] = h * Wf2[n * OUT_ + 0];
    s1[n] = h * Wf2[n * OUT_ + 1];
    __syncthreads();
    for (int off = HID_ / 2; off > 0; off >>= 1) {
        if (n < off) { s0[n] += s0[n + off]; s1[n] += s1[n + off]; }
        __syncthreads();
    }
    if (n == 0) {
        out[g * OUT_ + 0] = s0[0] + bf2[0];
        out[g * OUT_ + 1] = s1[0] + bf2[1];
    }
}

// ---------------- launch ----------------
extern "C" void kernel_launch(void* const* d_in, const int* in_sizes, int n_in,
                              void* d_out, int out_size)
{
    (void)in_sizes; (void)n_in; (void)out_size;

    const float* edge_attr = (const float*)d_in[0];
    const float* arr       = (const float*)d_in[1];
    const int*   eidx      = (const int*)d_in[2];
    const int*   batch     = (const int*)d_in[3];
    const float *W1 = (const float*)d_in[4],  *b1 = (const float*)d_in[5];
    const float *g1 = (const float*)d_in[6],  *be1 = (const float*)d_in[7];
    const float *m1 = (const float*)d_in[8],  *v1 = (const float*)d_in[9];
    const float *W2 = (const float*)d_in[10], *b2 = (const float*)d_in[11];
    const float *g2 = (const float*)d_in[12], *be2 = (const float*)d_in[13];
    const float *m2 = (const float*)d_in[14], *v2 = (const float*)d_in[15];
    const float *W3 = (const float*)d_in[16], *b3 = (const float*)d_in[17];
    const float *g3 = (const float*)d_in[18], *be3 = (const float*)d_in[19];
    const float *m3 = (const float*)d_in[20], *v3 = (const float*)d_in[21];
    const float *Wf1 = (const float*)d_in[22], *bf1 = (const float*)d_in[23];
    const float *Wf2 = (const float*)d_in[24], *bf2 = (const float*)d_in[25];
    float* out = (float*)d_out;

    __half *a1, *h1, *h2, *w1t, *w2t, *w3t, *wf1t;
    float *s1p, *t1p, *s2p, *t2p;
    cudaGetSymbolAddress((void**)&a1,   g_A1);
    cudaGetSymbolAddress((void**)&h1,   g_h1);
    cudaGetSymbolAddress((void**)&h2,   g_h2);
    cudaGetSymbolAddress((void**)&w1t,  g_W1t);
    cudaGetSymbolAddress((void**)&w2t,  g_W2t);
    cudaGetSymbolAddress((void**)&w3t,  g_W3t);
    cudaGetSymbolAddress((void**)&wf1t, g_Wf1t);
    cudaGetSymbolAddress((void**)&s1p,  g_s1);
    cudaGetSymbolAddress((void**)&t1p,  g_t1);
    cudaGetSymbolAddress((void**)&s2p,  g_s2);
    cudaGetSymbolAddress((void**)&t2p,  g_t2);

    cudaFuncSetAttribute(gemm_f16, cudaFuncAttributeMaxDynamicSharedMemorySize,
                         STAGES * STAGE_BYTES);

    // prep
    prep0_kernel<<<32, 256>>>(g1, be1, m1, v1, g2, be2, m2, v2, g3, be3, m3, v3);
    prep_edge_kernel<<<E_ / 256, 256>>>(eidx, batch);
    prep_prefix_kernel<<<1, G_>>>();
    scatter_kernel<<<E_ / 256, 256>>>();
    build_a1_kernel<<<E_, 256>>>(edge_attr, arr, eidx);
    {
        dim3 gw((KP1 + 255) / 256, HP);
        prep_wt_kernel<<<gw, 256>>>(W1, KIN_, EMB_, w1t, KP1, 0);
    }
    {
        dim3 gw((HP + 255) / 256, HP);
        prep_wt_kernel<<<gw, 256>>>(W2, EMB_, EMB_, w2t, HP, 0);
        prep_wt_kernel<<<gw, 256>>>(W3, EMB_, EMB_, w3t, HP, 0);
    }
    {
        dim3 gw((HP + 255) / 256, HID_);
        prep_wt_kernel<<<gw, 256>>>(Wf1, EMB_, HID_, wf1t, HP, 1);
    }
    prep_c0_kernel<<<1, HID_>>>(Wf1);

    const int smem = STAGES * STAGE_BYTES;
    dim3 blk(128);
    dim3 grid5(5, E_ / 128);   // N=640 padded
    dim3 grid1(1, E_ / 128);

    // Layer 1: A1 @ W1t -> relu -> BN affine -> h1
    gemm_f16<<<grid5, blk, smem>>>(a1, KP1, w1t, KP1, b1, s1p, t1p,
                                   h1, HP, EMB_, KP1 / 64, 0);
    // Layer 2: h1 @ W2t -> relu -> BN affine -> h2
    gemm_f16<<<grid5, blk, smem>>>(h1, HP, w2t, HP, b2, s2p, t2p,
                                   h2, HP, EMB_, HP / 64, 0);
    // Layer 3: h2 @ W3t -> relu -> h1 (BN affine folded into Wf1t)
    gemm_f16<<<grid5, blk, smem>>>(h2, HP, w3t, HP, b3, nullptr, nullptr,
                                   h1, HP, EMB_, HP / 64, 1);
    // Pool projection: gathered (sorted) h1 rows @ Wf1t -> segment-sum into g_gsum
    gemm_f16<<<grid1, blk, smem>>>(h1, HP, wf1t, HP, nullptr, nullptr, nullptr,
                                   nullptr, 0, HID_, HP / 64, 2);
    // Head
    head_kernel<<<G_, HID_>>>(bf1, Wf2, bf2, out);
}

// round 9
// speedup vs baseline: 9.7012x; 1.0008x over previous
#include <cuda_runtime.h>
#include <cuda_fp16.h>
#include <cstdint>

// Problem constants
#define E_    131072
#define G_    64
#define ED_   2049
#define KIN_  2055
#define EMB_  625
#define HID_  128
#define OUT_  2
#define EPSF  1e-5f

#define KP1   2112     // padded K for layer 1 (multiple of 64)
#define HP    640      // padded N / K pitch for h buffers & weights
#define STAGES 3
#define STAGE_BYTES 32768   // A 16KB + B 16KB (128 rows x 128B, k-tile = 64 halves)

// ---------------- device scratch (allocation-free) ----------------
__device__ __half g_A1[(size_t)E_ * KP1];
__device__ __half g_h1[(size_t)E_ * HP];
__device__ __half g_h2[(size_t)E_ * HP];
__device__ __half g_W1t[HP * KP1];
__device__ __half g_W2t[HP * HP];
__device__ __half g_W3t[HP * HP];
__device__ __half g_Wf1t[HID_ * HP];
__device__ float g_s1[EMB_], g_t1[EMB_];
__device__ float g_s2[EMB_], g_t2[EMB_];
__device__ float g_s3[EMB_], g_t3[EMB_];
__device__ float g_c0[HID_];
__device__ int   g_ebatch[E_];     // batch id per edge (original order)
__device__ int   g_perm[E_];       // sorted-pos -> original edge
__device__ int   g_ebatch_s[E_];   // batch id per sorted pos
__device__ int   g_bcnt[G_];
__device__ int   g_bpos[G_];
__device__ float g_cnt[G_];
__device__ float g_gsum[G_ * HID_];

// ---------------- helpers ----------------
__device__ __forceinline__ uint32_t smem_u32(const void* p) {
    return (uint32_t)__cvta_generic_to_shared(p);
}
__device__ __forceinline__ void cp16(uint32_t dst, const void* src) {
    asm volatile("cp.async.cg.shared.global [%0], [%1], 16;\n" :: "r"(dst), "l"(src));
}
#define CP_COMMIT() asm volatile("cp.async.commit_group;\n" ::: "memory")
#define CP_WAIT2()  asm volatile("cp.async.wait_group 2;\n" ::: "memory")

__device__ __forceinline__ void ldsm4(uint32_t& r0, uint32_t& r1, uint32_t& r2, uint32_t& r3,
                                      uint32_t addr) {
    asm volatile("ldmatrix.sync.aligned.m8n8.x4.shared.b16 {%0,%1,%2,%3}, [%4];"
                 : "=r"(r0), "=r"(r1), "=r"(r2), "=r"(r3) : "r"(addr));
}

#define MMA_F16(d, a, b0, b1)                                           \
    asm volatile(                                                       \
        "mma.sync.aligned.m16n8k16.row.col.f32.f16.f16.f32 "            \
        "{%0,%1,%2,%3}, {%4,%5,%6,%7}, {%8,%9}, {%0,%1,%2,%3};"         \
        : "+f"(d[0]), "+f"(d[1]), "+f"(d[2]), "+f"(d[3])                \
        : "r"(a[0]), "r"(a[1]), "r"(a[2]), "r"(a[3]), "r"(b0), "r"(b1))

// ---------------- prep kernels ----------------
__global__ void prep0_kernel(const float* __restrict__ g1, const float* __restrict__ be1,
                             const float* __restrict__ m1, const float* __restrict__ v1,
                             const float* __restrict__ g2, const float* __restrict__ be2,
                             const float* __restrict__ m2, const float* __restrict__ v2,
                             const float* __restrict__ g3, const float* __restrict__ be3,
                             const float* __restrict__ m3, const float* __restrict__ v3)
{
    int i = blockIdx.x * blockDim.x + threadIdx.x;
    if (i < EMB_) {
        float s1 = g1[i] / sqrtf(v1[i] + EPSF);
        g_s1[i] = s1; g_t1[i] = be1[i] - m1[i] * s1;
        float s2 = g2[i] / sqrtf(v2[i] + EPSF);
        g_s2[i] = s2; g_t2[i] = be2[i] - m2[i] * s2;
        float s3 = g3[i] / sqrtf(v3[i] + EPSF);
        g_s3[i] = s3; g_t3[i] = be3[i] - m3[i] * s3;
    }
    if (i < G_) g_bcnt[i] = 0;
    if (i < G_ * HID_) g_gsum[i] = 0.0f;
}

__global__ void prep_edge_kernel(const int* __restrict__ eidx,
                                 const int* __restrict__ batch)
{
    __shared__ int hist[G_];
    int t = threadIdx.x;
    if (t < G_) hist[t] = 0;
    __syncthreads();
    int e = blockIdx.x * blockDim.x + t;
    int b = batch[eidx[e]];
    g_ebatch[e] = b;
    atomicAdd(&hist[b], 1);
    __syncthreads();
    if (t < G_) atomicAdd(&g_bcnt[t], hist[t]);
}

__global__ void prep_prefix_kernel()   // 1 block, 64 threads
{
    __shared__ int s[G_];
    int t = threadIdx.x;
    int c = g_bcnt[t];
    s[t] = c;
    __syncthreads();
    int off = 0;
    for (int i = 0; i < t; i++) off += s[i];
    g_bpos[t] = off;
    g_cnt[t] = (float)c;
}

__global__ void scatter_kernel()
{
    int e = blockIdx.x * blockDim.x + threadIdx.x;
    int b = g_ebatch[e];
    int pos = atomicAdd(&g_bpos[b], 1);
    g_perm[pos] = e;
    g_ebatch_s[pos] = b;
}

// Build fp16 concatenated A1[e][0..KP1), vectorized stores (uint2 = 4 halves)
__global__ void build_a1_kernel(const float* __restrict__ ea,
                                const float* __restrict__ arr,
                                const int* __restrict__ eidx)
{
    const int e = blockIdx.x;
    const float* src = ea + (size_t)e * ED_;
    __half* dst = g_A1 + (size_t)e * KP1;
    const int t = threadIdx.x;

    // k in [0, 2048): 512 groups of 4
    for (int q = t; q < 512; q += blockDim.x) {
        int k = q * 4;
        float f0 = src[k], f1 = src[k + 1], f2 = src[k + 2], f3 = src[k + 3];
        __half2 p0 = __floats2half2_rn(f0, f1);
        __half2 p1 = __floats2half2_rn(f2, f3);
        uint2 u;
        u.x = *(uint32_t*)&p0;
        u.y = *(uint32_t*)&p1;
        *(uint2*)(dst + k) = u;
    }
    // tail: k in [2048, 2112)
    if (t < 64) {
        int k = 2048 + t;
        float v;
        if (k < ED_) {
            v = src[k];
        } else if (k < ED_ + 3) {
            v = arr[3 * eidx[e] + (k - ED_)];
        } else if (k < ED_ + 6) {
            v = arr[3 * eidx[E_ + e] + (k - ED_ - 3)];
        } else {
            v = 0.0f;
        }
        dst[k] = __float2half_rn(v);
    }
}

// Wt[n][k] = fp16( W[k][n] * (scale_k ? s3[k] : 1) ), zero-padded to [NP][KP]
__global__ void prep_wt_kernel(const float* __restrict__ W, int K, int N,
                               __half* __restrict__ Wt, int KP, int scale_k)
{
    int k = blockIdx.x * blockDim.x + threadIdx.x;
    int n = blockIdx.y;
    if (k >= KP) return;
    float v = 0.0f;
    if (k < K && n < N) {
        v = W[(size_t)k * N + n];
        if (scale_k) v *= g_s3[k];
    }
    Wt[(size_t)n * KP + k] = __float2half_rn(v);
}

// c0[n] = t3 @ Wf1[:, n]  (constant from layer-3 BN fold), computed once
__global__ void prep_c0_kernel(const float* __restrict__ Wf1)
{
    int n = threadIdx.x;
    float c0 = 0.0f;
    for (int k = 0; k < EMB_; k++) c0 = fmaf(g_t3[k], Wf1[k * HID_ + n], c0);
    g_c0[n] = c0;
}

// ---------------- fp16 tensor-core GEMM: cp.async pipeline + ldmatrix ----------------
//   emode 0: h = max(z + bias, 0) * scale + shift  -> fp16 store (0 for n >= Nreal)
//   emode 1: h = max(z + bias, 0)                  -> fp16 store
//   emode 2: rows gathered via g_perm (sorted by batch); segment-sum into g_gsum
__global__ __launch_bounds__(128)
void gemm_f16(const __half* __restrict__ A, int lda,
              const __half* __restrict__ Bt, int ldbt,
              const float* __restrict__ bias,
              const float* __restrict__ scale,
              const float* __restrict__ shift,
              __half* __restrict__ C, int ldc,
              int Nreal, int ktiles, int emode)
{
    extern __shared__ __align__(16) char smem_raw[];
    const uint32_t sb = smem_u32(smem_raw);

    const int tid  = threadIdx.x;
    const int lane = tid & 31;
    const int w    = tid >> 5;            // 0..3
    const int wm   = (w & 1) * 64;
    const int wn   = (w >> 1) * 64;
    const int row0 = blockIdx.y * 128;
    const int col0 = blockIdx.x * 128;

    const __half* Abase = A  + (size_t)row0 * lda;
    const __half* Bbase = Bt + (size_t)col0 * ldbt;

    // per-thread gathered row pointers for pool GEMM (constant across ktiles)
    const __half* arow[8];
    if (emode == 2) {
#pragma unroll
        for (int i = 0; i < 8; i++) {
            int m = (i * 128 + tid) >> 3;
            arow[i] = A + (size_t)g_perm[row0 + m] * lda;
        }
    }

    // ldmatrix lane address components
    const int rA  = wm + (lane & 15);
    const int hiA = lane >> 4;
    const int xa  = rA & 7;
    const int rB  = wn + ((lane >> 4) & 1) * 8 + (lane & 7);
    const int hiB = (lane >> 3) & 1;
    const int xb  = rB & 7;

    float acc[4][8][4];
#pragma unroll
    for (int mi = 0; mi < 4; mi++)
#pragma unroll
        for (int ni = 0; ni < 8; ni++)
#pragma unroll
            for (int c = 0; c < 4; c++) acc[mi][ni][c] = 0.0f;

    auto stage = [&](int s, int kt) {
        uint32_t sA = sb + s * STAGE_BYTES;
        uint32_t sB = sA + 16384;
        const __half* Ak = Abase + kt * 64;
        const __half* Bk = Bbase + kt * 64;
#pragma unroll
        for (int i = 0; i < 8; i++) {
            int id = i * 128 + tid;
            int m  = id >> 3;
            int c  = id & 7;
            const __half* srcA = (emode == 2) ? (arow[i] + kt * 64 + c * 8)
                                              : (Ak + (size_t)m * lda + c * 8);
            cp16(sA + m * 128 + ((c ^ (m & 7)) << 4), srcA);
        }
#pragma unroll
        for (int i = 0; i < 8; i++) {
            int id = i * 128 + tid;
            int n  = id >> 3;
            int c  = id & 7;
            cp16(sB + n * 128 + ((c ^ (n & 7)) << 4), Bk + (size_t)n * ldbt + c * 8);
        }
    };

#pragma unroll
    for (int s = 0; s < STAGES - 1; s++) {
        if (s < ktiles) stage(s, s);
        CP_COMMIT();
    }

    for (int kt = 0; kt < ktiles; kt++) {
        int pf = kt + STAGES - 1;
        if (pf < ktiles) stage(pf % STAGES, pf);
        CP_COMMIT();
        CP_WAIT2();
        __syncthreads();

        const int s = kt % STAGES;
        const uint32_t sA = sb + s * STAGE_BYTES;
        const uint32_t sB = sA + 16384;

#pragma unroll
        for (int k16 = 0; k16 < 4; k16++) {
            uint32_t a[4][4];
#pragma unroll
            for (int mi = 0; mi < 4; mi++) {
                uint32_t addr = sA + (rA + mi * 16) * 128
                              + ((uint32_t)((k16 * 2 + hiA) ^ xa) << 4);
                ldsm4(a[mi][0], a[mi][1], a[mi][2], a[mi][3], addr);
            }
            uint32_t bf[4][4];
#pragma unroll
            for (int nj = 0; nj < 4; nj++) {
                uint32_t addr = sB + (rB + nj * 16) * 128
                              + ((uint32_t)((k16 * 2 + hiB) ^ xb) << 4);
                ldsm4(bf[nj][0], bf[nj][1], bf[nj][2], bf[nj][3], addr);
            }
#pragma unroll
            for (int mi = 0; mi < 4; mi++) {
#pragma unroll
                for (int nj = 0; nj < 4; nj++) {
                    MMA_F16(acc[mi][2 * nj],     a[mi], bf[nj][0], bf[nj][1]);
                    MMA_F16(acc[mi][2 * nj + 1], a[mi], bf[nj][2], bf[nj][3]);
                }
            }
        }
        __syncthreads();
    }

    // ---- epilogue ----
    const int g  = lane >> 2;
    const int tg = lane & 3;
    if (emode == 2) {
        const int b0 = g_ebatch_s[row0];
        const int bL = g_ebatch_s[row0 + 127];
        if (b0 == bL) {
            // uniform tile: reduce all 128 rows, 128 atomics total
            float s[8][2];
#pragma unroll
            for (int ni = 0; ni < 8; ni++) {
                s[ni][0] = 0.0f; s[ni][1] = 0.0f;
#pragma unroll
                for (int mi = 0; mi < 4; mi++) {
                    s[ni][0] += acc[mi][ni][0] + acc[mi][ni][2];
                    s[ni][1] += acc[mi][ni][1] + acc[mi][ni][3];
                }
            }
#pragma unroll
            for (int off = 4; off <= 16; off <<= 1) {
#pragma unroll
                for (int ni = 0; ni < 8; ni++) {
                    s[ni][0] += __shfl_xor_sync(0xffffffffu, s[ni][0], off);
                    s[ni][1] += __shfl_xor_sync(0xffffffffu, s[ni][1], off);
                }
            }
            __shared__ float red[2][128];
            if (lane < 4) {
#pragma unroll
                for (int ni = 0; ni < 8; ni++) {
                    red[wm >> 6][wn + ni * 8 + lane * 2 + 0] = s[ni][0];
                    red[wm >> 6][wn + ni * 8 + lane * 2 + 1] = s[ni][1];
                }
            }
            __syncthreads();
            atomicAdd(&g_gsum[b0 * HID_ + tid], red[0][tid] + red[1][tid]);
        } else {
            // mixed tile (rare): per-row atomics
#pragma unroll
            for (int mi = 0; mi < 4; mi++) {
                int r_lo = row0 + wm + mi * 16 + g;
                int b_lo = g_ebatch_s[r_lo];
                int b_hi = g_ebatch_s[r_lo + 8];
#pragma unroll
                for (int ni = 0; ni < 8; ni++) {
                    int cc = wn + ni * 8 + tg * 2;
                    atomicAdd(&g_gsum[b_lo * HID_ + cc],     acc[mi][ni][0]);
                    atomicAdd(&g_gsum[b_lo * HID_ + cc + 1], acc[mi][ni][1]);
                    atomicAdd(&g_gsum[b_hi * HID_ + cc],     acc[mi][ni][2]);
                    atomicAdd(&g_gsum[b_hi * HID_ + cc + 1], acc[mi][ni][3]);
                }
            }
        }
    } else {
#pragma unroll
        for (int mi = 0; mi < 4; mi++) {
            int r_lo = row0 + wm + mi * 16 + g;
            __half* crow_lo = C + (size_t)r_lo * ldc;
            __half* crow_hi = crow_lo + (size_t)8 * ldc;
#pragma unroll
            for (int ni = 0; ni < 8; ni++) {
                int cc = col0 + wn + ni * 8 + tg * 2;
                float z0 = 0.0f, z1 = 0.0f, z2 = 0.0f, z3 = 0.0f;
                if (cc < Nreal) {
                    float b0 = bias[cc];
                    z0 = fmaxf(acc[mi][ni][0] + b0, 0.0f);
                    z2 = fmaxf(acc[mi][ni][2] + b0, 0.0f);
                    if (emode == 0) {
                        float sc0 = scale[cc], sh0 = shift[cc];
                        z0 = z0 * sc0 + sh0;  z2 = z2 * sc0 + sh0;
                    }
                }
                if (cc + 1 < Nreal) {
                    float b1 = bias[cc + 1];
                    z1 = fmaxf(acc[mi][ni][1] + b1, 0.0f);
                    z3 = fmaxf(acc[mi][ni][3] + b1, 0.0f);
                    if (emode == 0) {
                        float sc1 = scale[cc + 1], sh1 = shift[cc + 1];
                        z1 = z1 * sc1 + sh1;  z3 = z3 * sc1 + sh1;
                    }
                }
                *(__half2*)&crow_lo[cc] = __floats2half2_rn(z0, z1);
                *(__half2*)&crow_hi[cc] = __floats2half2_rn(z2, z3);
            }
        }
    }
}

// ---------------- head: mean + 2-layer MLP ----------------
__global__ void head_kernel(const float* __restrict__ bf1,
                            const float* __restrict__ Wf2,
                            const float* __restrict__ bf2,
                            float* __restrict__ out)
{
    const int g = blockIdx.x;
    const int n = threadIdx.x;
    float cnt = g_cnt[g];
    float v = (cnt > 0.0f) ? (g_gsum[g * HID_ + n] / cnt + g_c0[n]) : 0.0f;
    float h = fmaxf(v + bf1[n], 0.0f);

    __shared__ float s0[HID_], s1[HID_];
    s0[n] = h * Wf2[n * OUT_ + 0];
    s1[n] = h * Wf2[n * OUT_ + 1];
    __syncthreads();
    for (int off = HID_ / 2; off > 0; off >>= 1) {
        if (n < off) { s0[n] += s0[n + off]; s1[n] += s1[n + off]; }
        __syncthreads();
    }
    if (n == 0) {
        out[g * OUT_ + 0] = s0[0] + bf2[0];
        out[g * OUT_ + 1] = s1[0] + bf2[1];
    }
}

// ---------------- launch ----------------
extern "C" void kernel_launch(void* const* d_in, const int* in_sizes, int n_in,
                              void* d_out, int out_size)
{
    (void)in_sizes; (void)n_in; (void)out_size;

    const float* edge_attr = (const float*)d_in[0];
    const float* arr       = (const float*)d_in[1];
    const int*   eidx      = (const int*)d_in[2];
    const int*   batch     = (const int*)d_in[3];
    const float *W1 = (const float*)d_in[4],  *b1 = (const float*)d_in[5];
    const float *g1 = (const float*)d_in[6],  *be1 = (const float*)d_in[7];
    const float *m1 = (const float*)d_in[8],  *v1 = (const float*)d_in[9];
    const float *W2 = (const float*)d_in[10], *b2 = (const float*)d_in[11];
    const float *g2 = (const float*)d_in[12], *be2 = (const float*)d_in[13];
    const float *m2 = (const float*)d_in[14], *v2 = (const float*)d_in[15];
    const float *W3 = (const float*)d_in[16], *b3 = (const float*)d_in[17];
    const float *g3 = (const float*)d_in[18], *be3 = (const float*)d_in[19];
    const float *m3 = (const float*)d_in[20], *v3 = (const float*)d_in[21];
    const float *Wf1 = (const float*)d_in[22], *bf1 = (const float*)d_in[23];
    const float *Wf2 = (const float*)d_in[24], *bf2 = (const float*)d_in[25];
    float* out = (float*)d_out;

    __half *a1, *h1, *h2, *w1t, *w2t, *w3t, *wf1t;
    float *s1p, *t1p, *s2p, *t2p;
    cudaGetSymbolAddress((void**)&a1,   g_A1);
    cudaGetSymbolAddress((void**)&h1,   g_h1);
    cudaGetSymbolAddress((void**)&h2,   g_h2);
    cudaGetSymbolAddress((void**)&w1t,  g_W1t);
    cudaGetSymbolAddress((void**)&w2t,  g_W2t);
    cudaGetSymbolAddress((void**)&w3t,  g_W3t);
    cudaGetSymbolAddress((void**)&wf1t, g_Wf1t);
    cudaGetSymbolAddress((void**)&s1p,  g_s1);
    cudaGetSymbolAddress((void**)&t1p,  g_t1);
    cudaGetSymbolAddress((void**)&s2p,  g_s2);
    cudaGetSymbolAddress((void**)&t2p,  g_t2);

    cudaFuncSetAttribute(gemm_f16, cudaFuncAttributeMaxDynamicSharedMemorySize,
                         STAGES * STAGE_BYTES);

    // prep
    prep0_kernel<<<32, 256>>>(g1, be1, m1, v1, g2, be2, m2, v2, g3, be3, m3, v3);
    prep_edge_kernel<<<E_ / 256, 256>>>(eidx, batch);
    prep_prefix_kernel<<<1, G_>>>();
    scatter_kernel<<<E_ / 256, 256>>>();
    build_a1_kernel<<<E_, 256>>>(edge_attr, arr, eidx);
    {
        dim3 gw((KP1 + 255) / 256, HP);
        prep_wt_kernel<<<gw, 256>>>(W1, KIN_, EMB_, w1t, KP1, 0);
    }
    {
        dim3 gw((HP + 255) / 256, HP);
        prep_wt_kernel<<<gw, 256>>>(W2, EMB_, EMB_, w2t, HP, 0);
        prep_wt_kernel<<<gw, 256>>>(W3, EMB_, EMB_, w3t, HP, 0);
    }
    {
        dim3 gw((HP + 255) / 256, HID_);
        prep_wt_kernel<<<gw, 256>>>(Wf1, EMB_, HID_, wf1t, HP, 1);
    }
    prep_c0_kernel<<<1, HID_>>>(Wf1);

    const int smem = STAGES * STAGE_BYTES;
    dim3 blk(128);
    dim3 grid5(5, E_ / 128);   // N=640 padded
    dim3 grid1(1, E_ / 128);

    // Layer 1: A1 @ W1t -> relu -> BN affine -> h1
    gemm_f16<<<grid5, blk, smem>>>(a1, KP1, w1t, KP1, b1, s1p, t1p,
                                   h1, HP, EMB_, KP1 / 64, 0);
    // Layer 2: h1 @ W2t -> relu -> BN affine -> h2
    gemm_f16<<<grid5, blk, smem>>>(h1, HP, w2t, HP, b2, s2p, t2p,
                                   h2, HP, EMB_, HP / 64, 0);
    // Layer 3: h2 @ W3t -> relu -> h1 (BN affine folded into Wf1t)
    gemm_f16<<<grid5, blk, smem>>>(h2, HP, w3t, HP, b3, nullptr, nullptr,
                                   h1, HP, EMB_, HP / 64, 1);
    // Pool projection: gathered (sorted) h1 rows @ Wf1t -> segment-sum into g_gsum
    gemm_f16<<<grid1, blk, smem>>>(h1, HP, wf1t, HP, nullptr, nullptr, nullptr,
                                   nullptr, 0, HID_, HP / 64, 2);
    // Head
    head_kernel<<<G_, HID_>>>(bf1, Wf2, bf2, out);
}

// round 10
// speedup vs baseline: 9.9633x; 1.0270x over previous
#include <cuda_runtime.h>
#include <cuda_fp16.h>
#include <cstdint>

// Problem constants
#define E_    131072
#define G_    64
#define ED_   2049
#define KIN_  2055
#define EMB_  625
#define HID_  128
#define OUT_  2
#define EPSF  1e-5f

#define KP1   2112     // padded K for layer 1 (multiple of 64)
#define HP    640      // padded N / K pitch for h buffers & weights
#define STAGES 3
#define STAGE_BYTES 32768   // A 16KB + B 16KB (128 rows x 128B, k-tile = 64 halves)
#define NBLK  512           // E_/256 edge-processing blocks

// ---------------- device scratch (allocation-free) ----------------
__device__ __half g_A1[(size_t)E_ * KP1];
__device__ __half g_h1[(size_t)E_ * HP];
__device__ __half g_h2[(size_t)E_ * HP];
__device__ __half g_W1t[HP * KP1];
__device__ __half g_W2t[HP * HP];
__device__ __half g_W3t[HP * HP];
__device__ __half g_Wf1t[HID_ * HP];
__device__ float g_s1[EMB_], g_t1[EMB_];
__device__ float g_s2[EMB_], g_t2[EMB_];
__device__ float g_s3[EMB_], g_t3[EMB_];
__device__ float g_c0[HID_];
__device__ int   g_ebatch[E_];       // batch id per edge (original order)
__device__ int   g_perm[E_];         // sorted-pos -> original edge
__device__ int   g_ebatch_s[E_];     // batch id per sorted pos
__device__ int   g_bhist[NBLK * G_]; // per-block hist -> per-block base
__device__ float g_cnt[G_];
__device__ float g_gsum[G_ * HID_];

// ---------------- helpers ----------------
__device__ __forceinline__ uint32_t smem_u32(const void* p) {
    return (uint32_t)__cvta_generic_to_shared(p);
}
__device__ __forceinline__ void cp16(uint32_t dst, const void* src) {
    asm volatile("cp.async.cg.shared.global [%0], [%1], 16;\n" :: "r"(dst), "l"(src));
}
#define CP_COMMIT() asm volatile("cp.async.commit_group;\n" ::: "memory")
#define CP_WAIT1()  asm volatile("cp.async.wait_group 1;\n" ::: "memory")

__device__ __forceinline__ void ldsm4(uint32_t& r0, uint32_t& r1, uint32_t& r2, uint32_t& r3,
                                      uint32_t addr) {
    asm volatile("ldmatrix.sync.aligned.m8n8.x4.shared.b16 {%0,%1,%2,%3}, [%4];"
                 : "=r"(r0), "=r"(r1), "=r"(r2), "=r"(r3) : "r"(addr));
}

#define MMA_F16(d, a, b0, b1)                                           \
    asm volatile(                                                       \
        "mma.sync.aligned.m16n8k16.row.col.f32.f16.f16.f32 "            \
        "{%0,%1,%2,%3}, {%4,%5,%6,%7}, {%8,%9}, {%0,%1,%2,%3};"         \
        : "+f"(d[0]), "+f"(d[1]), "+f"(d[2]), "+f"(d[3])                \
        : "r"(a[0]), "r"(a[1]), "r"(a[2]), "r"(a[3]), "r"(b0), "r"(b1))

// ---------------- prep kernels ----------------
__global__ void prep0_kernel(const float* __restrict__ g1, const float* __restrict__ be1,
                             const float* __restrict__ m1, const float* __restrict__ v1,
                             const float* __restrict__ g2, const float* __restrict__ be2,
                             const float* __restrict__ m2, const float* __restrict__ v2,
                             const float* __restrict__ g3, const float* __restrict__ be3,
                             const float* __restrict__ m3, const float* __restrict__ v3)
{
    int i = blockIdx.x * blockDim.x + threadIdx.x;
    if (i < EMB_) {
        float s1 = g1[i] / sqrtf(v1[i] + EPSF);
        g_s1[i] = s1; g_t1[i] = be1[i] - m1[i] * s1;
        float s2 = g2[i] / sqrtf(v2[i] + EPSF);
        g_s2[i] = s2; g_t2[i] = be2[i] - m2[i] * s2;
        float s3 = g3[i] / sqrtf(v3[i] + EPSF);
        g_s3[i] = s3; g_t3[i] = be3[i] - m3[i] * s3;
    }
    if (i < G_ * HID_) g_gsum[i] = 0.0f;
}

// per-block histogram of batch ids (no global atomics)
__global__ void prep_edge_kernel(const int* __restrict__ eidx,
                                 const int* __restrict__ batch)
{
    __shared__ int hist[G_];
    int t = threadIdx.x;
    if (t < G_) hist[t] = 0;
    __syncthreads();
    int e = blockIdx.x * blockDim.x + t;
    int b = batch[eidx[e]];
    g_ebatch[e] = b;
    atomicAdd(&hist[b], 1);
    __syncthreads();
    if (t < G_) g_bhist[blockIdx.x * G_ + t] = hist[t];
}

// column prefix: g_bhist[blk][b] -> global base for (blk, b); g_cnt[b] = total
__global__ void prep_prefix_kernel()   // 1 block, 64 threads
{
    __shared__ int tot[G_];
    int b = threadIdx.x;
    int t = 0;
    for (int blk = 0; blk < NBLK; blk++) t += g_bhist[blk * G_ + b];
    tot[b] = t;
    g_cnt[b] = (float)t;
    __syncthreads();
    int off = 0;
    for (int i = 0; i < b; i++) off += tot[i];
    int run = off;
    for (int blk = 0; blk < NBLK; blk++) {
        int h = g_bhist[blk * G_ + b];
        g_bhist[blk * G_ + b] = run;
        run += h;
    }
}

__global__ void scatter_kernel()
{
    __shared__ int cnt[G_];
    int t = threadIdx.x;
    if (t < G_) cnt[t] = 0;
    __syncthreads();
    int e = blockIdx.x * blockDim.x + t;
    int b = g_ebatch[e];
    int r = atomicAdd(&cnt[b], 1);
    int pos = g_bhist[blockIdx.x * G_ + b] + r;
    g_perm[pos] = e;
    g_ebatch_s[pos] = b;
}

// Build fp16 concatenated A1[e][0..KP1), vectorized stores (uint2 = 4 halves)
__global__ void build_a1_kernel(const float* __restrict__ ea,
                                const float* __restrict__ arr,
                                const int* __restrict__ eidx)
{
    const int e = blockIdx.x;
    const float* src = ea + (size_t)e * ED_;
    __half* dst = g_A1 + (size_t)e * KP1;
    const int t = threadIdx.x;

    for (int q = t; q < 512; q += blockDim.x) {
        int k = q * 4;
        float f0 = src[k], f1 = src[k + 1], f2 = src[k + 2], f3 = src[k + 3];
        __half2 p0 = __floats2half2_rn(f0, f1);
        __half2 p1 = __floats2half2_rn(f2, f3);
        uint2 u;
        u.x = *(uint32_t*)&p0;
        u.y = *(uint32_t*)&p1;
        *(uint2*)(dst + k) = u;
    }
    if (t < 64) {
        int k = 2048 + t;
        float v;
        if (k < ED_) {
            v = src[k];
        } else if (k < ED_ + 3) {
            v = arr[3 * eidx[e] + (k - ED_)];
        } else if (k < ED_ + 6) {
            v = arr[3 * eidx[E_ + e] + (k - ED_ - 3)];
        } else {
            v = 0.0f;
        }
        dst[k] = __float2half_rn(v);
    }
}

// All four transposed weights in one launch (flat index, k-fast per segment)
#define WSEG1 ((size_t)HP * KP1)
#define WSEG2 (WSEG1 + (size_t)HP * HP)
#define WSEG3 (WSEG2 + (size_t)HP * HP)
#define WSEG4 (WSEG3 + (size_t)HID_ * HP)
__global__ void prep_wt_all(const float* __restrict__ W1, const float* __restrict__ W2,
                            const float* __restrict__ W3, const float* __restrict__ Wf1)
{
    size_t idx = (size_t)blockIdx.x * blockDim.x + threadIdx.x;
    if (idx < WSEG1) {
        int n = (int)(idx / KP1), k = (int)(idx % KP1);
        float v = (k < KIN_ && n < EMB_) ? W1[(size_t)k * EMB_ + n] : 0.0f;
        g_W1t[idx] = __float2half_rn(v);
    } else if (idx < WSEG2) {
        size_t j = idx - WSEG1;
        int n = (int)(j / HP), k = (int)(j % HP);
        float v = (k < EMB_ && n < EMB_) ? W2[(size_t)k * EMB_ + n] : 0.0f;
        g_W2t[j] = __float2half_rn(v);
    } else if (idx < WSEG3) {
        size_t j = idx - WSEG2;
        int n = (int)(j / HP), k = (int)(j % HP);
        float v = (k < EMB_ && n < EMB_) ? W3[(size_t)k * EMB_ + n] : 0.0f;
        g_W3t[j] = __float2half_rn(v);
    } else if (idx < WSEG4) {
        size_t j = idx - WSEG3;
        int n = (int)(j / HP), k = (int)(j % HP);
        float v = (k < EMB_ && n < HID_) ? Wf1[(size_t)k * HID_ + n] * g_s3[k] : 0.0f;
        g_Wf1t[j] = __float2half_rn(v);
    }
}

// c0[n] = t3 @ Wf1[:, n]
__global__ void prep_c0_kernel(const float* __restrict__ Wf1)
{
    int n = threadIdx.x;
    float c0 = 0.0f;
    for (int k = 0; k < EMB_; k++) c0 = fmaf(g_t3[k], Wf1[k * HID_ + n], c0);
    g_c0[n] = c0;
}

// ---------------- fp16 tensor-core GEMM: cp.async pipeline + ldmatrix ----------------
//   emode 0: h = max(z + bias, 0) * scale + shift  -> fp16 store (0 for n >= Nreal)
//   emode 1: h = max(z + bias, 0)                  -> fp16 store
//   emode 2: rows gathered via g_perm (sorted by batch); segment-sum into g_gsum
__global__ __launch_bounds__(128)
void gemm_f16(const __half* __restrict__ A, int lda,
              const __half* __restrict__ Bt, int ldbt,
              const float* __restrict__ bias,
              const float* __restrict__ scale,
              const float* __restrict__ shift,
              __half* __restrict__ C, int ldc,
              int Nreal, int ktiles, int emode)
{
    extern __shared__ __align__(16) char smem_raw[];
    const uint32_t sb = smem_u32(smem_raw);

    const int tid  = threadIdx.x;
    const int lane = tid & 31;
    const int w    = tid >> 5;            // 0..3
    const int wm   = (w & 1) * 64;
    const int wn   = (w >> 1) * 64;
    const int row0 = blockIdx.y * 128;
    const int col0 = blockIdx.x * 128;

    const __half* Abase = A  + (size_t)row0 * lda;
    const __half* Bbase = Bt + (size_t)col0 * ldbt;

    // per-thread gathered row pointers for pool GEMM (constant across ktiles)
    const __half* arow[8];
    if (emode == 2) {
#pragma unroll
        for (int i = 0; i < 8; i++) {
            int m = (i * 128 + tid) >> 3;
            arow[i] = A + (size_t)g_perm[row0 + m] * lda;
        }
    }

    // ldmatrix lane address components
    const int rA  = wm + (lane & 15);
    const int hiA = lane >> 4;
    const int xa  = rA & 7;
    const int rB  = wn + ((lane >> 4) & 1) * 8 + (lane & 7);
    const int hiB = (lane >> 3) & 1;
    const int xb  = rB & 7;

    float acc[4][8][4];
#pragma unroll
    for (int mi = 0; mi < 4; mi++)
#pragma unroll
        for (int ni = 0; ni < 8; ni++)
#pragma unroll
            for (int c = 0; c < 4; c++) acc[mi][ni][c] = 0.0f;

    auto stage = [&](int s, int kt) {
        uint32_t sA = sb + s * STAGE_BYTES;
        uint32_t sB = sA + 16384;
        const __half* Ak = Abase + kt * 64;
        const __half* Bk = Bbase + kt * 64;
#pragma unroll
        for (int i = 0; i < 8; i++) {
            int id = i * 128 + tid;
            int m  = id >> 3;
            int c  = id & 7;
            const __half* srcA = (emode == 2) ? (arow[i] + kt * 64 + c * 8)
                                              : (Ak + (size_t)m * lda + c * 8);
            cp16(sA + m * 128 + ((c ^ (m & 7)) << 4), srcA);
        }
#pragma unroll
        for (int i = 0; i < 8; i++) {
            int id = i * 128 + tid;
            int n  = id >> 3;
            int c  = id & 7;
            cp16(sB + n * 128 + ((c ^ (n & 7)) << 4), Bk + (size_t)n * ldbt + c * 8);
        }
    };

    // prologue: stages 0 and 1
    stage(0, 0);
    CP_COMMIT();
    stage(1, 1);
    CP_COMMIT();

    for (int kt = 0; kt < ktiles; kt++) {
        CP_WAIT1();          // stage kt arrived (allow kt+1 pending)
        __syncthreads();     // all threads past compute(kt-1) -> safe to overwrite its stage

        int pf = kt + 2;
        if (pf < ktiles) stage(pf % STAGES, pf);
        CP_COMMIT();

        const int s = kt % STAGES;
        const uint32_t sA = sb + s * STAGE_BYTES;
        const uint32_t sB = sA + 16384;

#pragma unroll
        for (int k16 = 0; k16 < 4; k16++) {
            uint32_t a[4][4];
#pragma unroll
            for (int mi = 0; mi < 4; mi++) {
                uint32_t addr = sA + (rA + mi * 16) * 128
                              + ((uint32_t)((k16 * 2 + hiA) ^ xa) << 4);
                ldsm4(a[mi][0], a[mi][1], a[mi][2], a[mi][3], addr);
            }
            uint32_t bf[4][4];
#pragma unroll
            for (int nj = 0; nj < 4; nj++) {
                uint32_t addr = sB + (rB + nj * 16) * 128
                              + ((uint32_t)((k16 * 2 + hiB) ^ xb) << 4);
                ldsm4(bf[nj][0], bf[nj][1], bf[nj][2], bf[nj][3], addr);
            }
#pragma unroll
            for (int mi = 0; mi < 4; mi++) {
#pragma unroll
                for (int nj = 0; nj < 4; nj++) {
                    MMA_F16(acc[mi][2 * nj],     a[mi], bf[nj][0], bf[nj][1]);
                    MMA_F16(acc[mi][2 * nj + 1], a[mi], bf[nj][2], bf[nj][3]);
                }
            }
        }
    }

    // ---- epilogue ----
    const int g  = lane >> 2;
    const int tg = lane & 3;
    if (emode == 2) {
        const int b0 = g_ebatch_s[row0];
        const int bL = g_ebatch_s[row0 + 127];
        if (b0 == bL) {
            float s[8][2];
#pragma unroll
            for (int ni = 0; ni < 8; ni++) {
                s[ni][0] = 0.0f; s[ni][1] = 0.0f;
#pragma unroll
                for (int mi = 0; mi < 4; mi++) {
                    s[ni][0] += acc[mi][ni][0] + acc[mi][ni][2];
                    s[ni][1] += acc[mi][ni][1] + acc[mi][ni][3];
                }
            }
#pragma unroll
            for (int off = 4; off <= 16; off <<= 1) {
#pragma unroll
                for (int ni = 0; ni < 8; ni++) {
                    s[ni][0] += __shfl_xor_sync(0xffffffffu, s[ni][0], off);
                    s[ni][1] += __shfl_xor_sync(0xffffffffu, s[ni][1], off);
                }
            }
            __shared__ float red[2][128];
            if (lane < 4) {
#pragma unroll
                for (int ni = 0; ni < 8; ni++) {
                    red[wm >> 6][wn + ni * 8 + lane * 2 + 0] = s[ni][0];
                    red[wm >> 6][wn + ni * 8 + lane * 2 + 1] = s[ni][1];
                }
            }
            __syncthreads();
            atomicAdd(&g_gsum[b0 * HID_ + tid], red[0][tid] + red[1][tid]);
        } else {
#pragma unroll
            for (int mi = 0; mi < 4; mi++) {
                int r_lo = row0 + wm + mi * 16 + g;
                int b_lo = g_ebatch_s[r_lo];
                int b_hi = g_ebatch_s[r_lo + 8];
#pragma unroll
                for (int ni = 0; ni < 8; ni++) {
                    int cc = wn + ni * 8 + tg * 2;
                    atomicAdd(&g_gsum[b_lo * HID_ + cc],     acc[mi][ni][0]);
                    atomicAdd(&g_gsum[b_lo * HID_ + cc + 1], acc[mi][ni][1]);
                    atomicAdd(&g_gsum[b_hi * HID_ + cc],     acc[mi][ni][2]);
                    atomicAdd(&g_gsum[b_hi * HID_ + cc + 1], acc[mi][ni][3]);
                }
            }
        }
    } else {
#pragma unroll
        for (int mi = 0; mi < 4; mi++) {
            int r_lo = row0 + wm + mi * 16 + g;
            __half* crow_lo = C + (size_t)r_lo * ldc;
            __half* crow_hi = crow_lo + (size_t)8 * ldc;
#pragma unroll
            for (int ni = 0; ni < 8; ni++) {
                int cc = col0 + wn + ni * 8 + tg * 2;
                float z0 = 0.0f, z1 = 0.0f, z2 = 0.0f, z3 = 0.0f;
                if (cc < Nreal) {
                    float b0 = bias[cc];
                    z0 = fmaxf(acc[mi][ni][0] + b0, 0.0f);
                    z2 = fmaxf(acc[mi][ni][2] + b0, 0.0f);
                    if (emode == 0) {
                        float sc0 = scale[cc], sh0 = shift[cc];
                        z0 = z0 * sc0 + sh0;  z2 = z2 * sc0 + sh0;
                    }
                }
                if (cc + 1 < Nreal) {
                    float b1 = bias[cc + 1];
                    z1 = fmaxf(acc[mi][ni][1] + b1, 0.0f);
                    z3 = fmaxf(acc[mi][ni][3] + b1, 0.0f);
                    if (emode == 0) {
                        float sc1 = scale[cc + 1], sh1 = shift[cc + 1];
                        z1 = z1 * sc1 + sh1;  z3 = z3 * sc1 + sh1;
                    }
                }
                *(__half2*)&crow_lo[cc] = __floats2half2_rn(z0, z1);
                *(__half2*)&crow_hi[cc] = __floats2half2_rn(z2, z3);
            }
        }
    }
}

// ---------------- head: mean + 2-layer MLP ----------------
__global__ void head_kernel(const float* __restrict__ bf1,
                            const float* __restrict__ Wf2,
                            const float* __restrict__ bf2,
                            float* __restrict__ out)
{
    const int g = blockIdx.x;
    const int n = threadIdx.x;
    float cnt = g_cnt[g];
    float v = (cnt > 0.0f) ? (g_gsum[g * HID_ + n] / cnt + g_c0[n]) : 0.0f;
    float h = fmaxf(v + bf1[n], 0.0f);

    __shared__ float s0[HID_], s1[HID_];
    s0[n] = h * Wf2[n * OUT_ + 0];
    s1[n] = h * Wf2[n * OUT_ + 1];
    __syncthreads();
    for (int off = HID_ / 2; off > 0; off >>= 1) {
        if (n < off) { s0[n] += s0[n + off]; s1[n] += s1[n + off]; }
        __syncthreads();
    }
    if (n == 0) {
        out[g * OUT_ + 0] = s0[0] + bf2[0];
        out[g * OUT_ + 1] = s1[0] + bf2[1];
    }
}

// ---------------- launch ----------------
extern "C" void kernel_launch(void* const* d_in, const int* in_sizes, int n_in,
                              void* d_out, int out_size)
{
    (void)in_sizes; (void)n_in; (void)out_size;

    const float* edge_attr = (const float*)d_in[0];
    const float* arr       = (const float*)d_in[1];
    const int*   eidx      = (const int*)d_in[2];
    const int*   batch     = (const int*)d_in[3];
    const float *W1 = (const float*)d_in[4],  *b1 = (const float*)d_in[5];
    const float *g1 = (const float*)d_in[6],  *be1 = (const float*)d_in[7];
    const float *m1 = (const float*)d_in[8],  *v1 = (const float*)d_in[9];
    const float *W2 = (const float*)d_in[10], *b2 = (const float*)d_in[11];
    const float *g2 = (const float*)d_in[12], *be2 = (const float*)d_in[13];
    const float *m2 = (const float*)d_in[14], *v2 = (const float*)d_in[15];
    const float *W3 = (const float*)d_in[16], *b3 = (const float*)d_in[17];
    const float *g3 = (const float*)d_in[18], *be3 = (const float*)d_in[19];
    const float *m3 = (const float*)d_in[20], *v3 = (const float*)d_in[21];
    const float *Wf1 = (const float*)d_in[22], *bf1 = (const float*)d_in[23];
    const float *Wf2 = (const float*)d_in[24], *bf2 = (const float*)d_in[25];
    float* out = (float*)d_out;

    __half *a1, *h1, *h2, *w1t, *w2t, *w3t, *wf1t;
    float *s1p, *t1p, *s2p, *t2p;
    cudaGetSymbolAddress((void**)&a1,   g_A1);
    cudaGetSymbolAddress((void**)&h1,   g_h1);
    cudaGetSymbolAddress((void**)&h2,   g_h2);
    cudaGetSymbolAddress((void**)&w1t,  g_W1t);
    cudaGetSymbolAddress((void**)&w2t,  g_W2t);
    cudaGetSymbolAddress((void**)&w3t,  g_W3t);
    cudaGetSymbolAddress((void**)&wf1t, g_Wf1t);
    cudaGetSymbolAddress((void**)&s1p,  g_s1);
    cudaGetSymbolAddress((void**)&t1p,  g_t1);
    cudaGetSymbolAddress((void**)&s2p,  g_s2);
    cudaGetSymbolAddress((void**)&t2p,  g_t2);

    cudaFuncSetAttribute(gemm_f16, cudaFuncAttributeMaxDynamicSharedMemorySize,
                         STAGES * STAGE_BYTES);

    // prep
    prep0_kernel<<<32, 256>>>(g1, be1, m1, v1, g2, be2, m2, v2, g3, be3, m3, v3);
    prep_edge_kernel<<<NBLK, 256>>>(eidx, batch);
    prep_prefix_kernel<<<1, G_>>>();
    scatter_kernel<<<NBLK, 256>>>();
    build_a1_kernel<<<E_, 256>>>(edge_attr, arr, eidx);
    prep_wt_all<<<(int)((WSEG4 + 255) / 256), 256>>>(W1, W2, W3, Wf1);
    prep_c0_kernel<<<1, HID_>>>(Wf1);

    const int smem = STAGES * STAGE_BYTES;
    dim3 blk(128);
    dim3 grid5(5, E_ / 128);   // N=640 padded
    dim3 grid1(1, E_ / 128);

    // Layer 1: A1 @ W1t -> relu -> BN affine -> h1
    gemm_f16<<<grid5, blk, smem>>>(a1, KP1, w1t, KP1, b1, s1p, t1p,
                                   h1, HP, EMB_, KP1 / 64, 0);
    // Layer 2: h1 @ W2t -> relu -> BN affine -> h2
    gemm_f16<<<grid5, blk, smem>>>(h1, HP, w2t, HP, b2, s2p, t2p,
                                   h2, HP, EMB_, HP / 64, 0);
    // Layer 3: h2 @ W3t -> relu -> h1 (BN affine folded into Wf1t)
    gemm_f16<<<grid5, blk, smem>>>(h2, HP, w3t, HP, b3, nullptr, nullptr,
                                   h1, HP, EMB_, HP / 64, 1);
    // Pool projection: gathered (sorted) h1 rows @ Wf1t -> segment-sum into g_gsum
    gemm_f16<<<grid1, blk, smem>>>(h1, HP, wf1t, HP, nullptr, nullptr, nullptr,
                                   nullptr, 0, HID_, HP / 64, 2);
    // Head
    head_kernel<<<G_, HID_>>>(bf1, Wf2, bf2, out);
}